// round 3
// baseline (speedup 1.0000x reference)
#include <cuda_runtime.h>

// ---------------- problem constants ----------------
#define F_    32
#define B_    6
#define P_    20
#define C_    1024
#define HF    14
#define NB    27
#define T_    5
#define OUTP  3
#define SPAT  9                 // 3x3
#define NBOX  (F_*B_)           // 192
#define K1    (C_*SPAT)         // 9216
#define N1    (3*512)           // 1536
#define M1    (NBOX*SPAT)       // 1728
#define K2    (512*27)          // 13824
#define M2    (NBOX*3)          // 576
#define N2    256
#define SPLIT2 12
#define KLEN2 (K2/SPLIT2)       // 1152

// ---------------- scratch (device globals; no runtime alloc) ----------------
__device__ int   g_map[NBOX*T_];                 // roi slice index or -1
__device__ float g_roi[NBOX*C_*SPAT];            // [192][1024][9]
__device__ float g_A1[(size_t)M1*K1];            // im2col of roi (spatial pad)
__device__ float g_B1[(size_t)K1*N1];            // w1a reordered
__device__ float g_P [(size_t)M1*N1];            // partial conv results
__device__ float g_y [(size_t)NBOX*5*SPAT*512];  // conv1a out, [n][d][sp][512]
__device__ float g_B2[(size_t)K2*N2];            // w1b reordered [(kd*9+sp)*512+ci][co2]
__device__ float g_C2p[(size_t)SPLIT2*M2*N2];    // conv1b split-K partials

// ---------------- 0: temporal index + person matching ----------------
__global__ void prep_map(const int* __restrict__ person_ids) {
    int n = threadIdx.x;
    if (n >= NBOX) return;
    int f = n / B_, b = n % B_;
    int pid = person_ids[f*B_ + b];
    int start = max(f - T_/2, 0);
    int end   = min(start + T_ - 1, F_ - 1);
    for (int t = 0; t < T_; t++) {
        int g = (int)((float)start + (float)(t*(end-start)) / (float)(T_-1));
        int m = -1;
        for (int bp = 0; bp < B_; bp++)
            if (person_ids[g*B_ + bp] == pid) m = g*B_ + bp;
        g_map[n*T_ + t] = m;
    }
}

// ---------------- 1: ROI align -> g_roi[192][1024][9] ----------------
__global__ void roi_kernel(const float* __restrict__ fmaps,
                           const float* __restrict__ boxes) {
    int nb = blockIdx.x;            // 0..191
    int f  = nb / B_;
    __shared__ int   sy0[6], sy1[6], sx0[6], sx1[6];
    __shared__ float sly[6], slx[6];
    if (threadIdx.x < 12) {
        int  j   = threadIdx.x % 6;
        bool isx = threadIdx.x >= 6;
        float x1 = boxes[nb*4+0], y1 = boxes[nb*4+1];
        float x2 = boxes[nb*4+2], y2 = boxes[nb*4+3];
        float bw = fmaxf(x2 - x1, 1.0f) / (float)OUTP;
        float bh = fmaxf(y2 - y1, 1.0f) / (float)OUTP;
        float gj = (float)(j >> 1) + ((float)(j & 1) + 0.5f) * 0.5f;
        if (isx) {
            float xs  = x1 + bw * gj;
            float x0f = fminf(fmaxf(floorf(xs), 0.f), (float)(HF-1));
            float lx  = fminf(fmaxf(xs - x0f, 0.f), 1.f);
            int x0 = (int)x0f;
            sx0[j] = x0; sx1[j] = min(x0+1, HF-1); slx[j] = lx;
        } else {
            float ys  = y1 + bh * gj;
            float y0f = fminf(fmaxf(floorf(ys), 0.f), (float)(HF-1));
            float ly  = fminf(fmaxf(ys - y0f, 0.f), 1.f);
            int y0 = (int)y0f;
            sy0[j] = y0; sy1[j] = min(y0+1, HF-1); sly[j] = ly;
        }
    }
    __syncthreads();
    const float* base = fmaps + (size_t)f * C_ * HF * HF;
    for (int idx = threadIdx.x; idx < C_*SPAT; idx += blockDim.x) {
        int c = idx / SPAT, o = idx % SPAT;
        int oi = o / 3, oj = o % 3;
        const float* fm = base + (size_t)c * HF * HF;
        float acc = 0.f;
        #pragma unroll
        for (int s = 0; s < 4; s++) {
            int jy = oi*2 + (s >> 1);
            int jx = oj*2 + (s & 1);
            float ly = sly[jy], lx = slx[jx];
            int y0 = sy0[jy], y1i = sy1[jy], x0 = sx0[jx], x1i = sx1[jx];
            acc += fm[y0*HF + x0]  * (1.f-ly)*(1.f-lx)
                 + fm[y0*HF + x1i] * (1.f-ly)*lx
                 + fm[y1i*HF + x0] * ly*(1.f-lx)
                 + fm[y1i*HF + x1i]* ly*lx;
        }
        g_roi[(size_t)nb*C_*SPAT + idx] = acc * 0.25f;
    }
}

// ---------------- 2: weight reorders (tiled transposes) ----------------
// w1a [co=512][ci=1024][kd=3][sp=9] -> B1 viewed [9216][1536]: k=ci*9+tap, n=kd*512+co
__global__ void t_w1a(const float* __restrict__ w) {
    __shared__ float tile[32][33];
    int r0 = blockIdx.x * 32;   // rest index over 27648 (ci*27 + kd*9 + tap)
    int c0 = blockIdx.y * 32;   // co
    int tx = threadIdx.x, ty = threadIdx.y;  // (32,8)
    for (int yy = ty; yy < 32; yy += 8)
        tile[yy][tx] = w[(size_t)(c0+yy)*27648 + r0 + tx];
    __syncthreads();
    for (int yy = ty; yy < 32; yy += 8) {
        int rin = r0 + yy;
        int ci = rin / 27, q = rin % 27;     // q = kd*9 + tap
        int rout = ci*27 + (q % 9)*3 + q/9;  // (ci*9+tap)*3 + kd
        g_B1[(size_t)rout*512 + c0 + tx] = tile[tx][yy];
    }
}
// w1b [co2=256][ci=512][kd=3][sp=9] -> B2 row=(kd*9+sp)*512+ci, col=co2
__global__ void t_w1b(const float* __restrict__ w) {
    __shared__ float tile[32][33];
    int r0 = blockIdx.x * 32;   // over 13824 (ci*27 + kd*9 + sp)
    int c0 = blockIdx.y * 32;   // co2
    int tx = threadIdx.x, ty = threadIdx.y;
    for (int yy = ty; yy < 32; yy += 8)
        tile[yy][tx] = w[(size_t)(c0+yy)*13824 + r0 + tx];
    __syncthreads();
    for (int yy = ty; yy < 32; yy += 8) {
        int rin = r0 + yy;
        int rout = (rin % 27)*512 + rin/27;
        g_B2[(size_t)rout*256 + c0 + tx] = tile[tx][yy];
    }
}

// ---------------- 3: im2col of roi with spatial zero-pad ----------------
__global__ void im2col_kernel() {
    int bid = blockIdx.x;           // 0..1727 = slice*9 + sp
    int r = bid / 9, sp = bid % 9;
    int h = sp / 3, w = sp % 3;
    float* dst = g_A1 + (size_t)bid * K1;
    const float* src = g_roi + (size_t)r * C_ * SPAT;
    for (int idx = threadIdx.x; idx < K1; idx += blockDim.x) {
        int ci = idx / 9, tap = idx % 9;
        int hi = h + tap/3 - 1, wi = w + tap%3 - 1;
        float v = 0.f;
        if (hi >= 0 && hi < 3 && wi >= 0 && wi < 3)
            v = src[ci*9 + hi*3 + wi];
        dst[idx] = v;
    }
}

// ---------------- 4: fp32 tiled GEMM, BM=128 BN=64 BK=16, 128 thr ----------
// Row remap: logical row r reads A at physical row roff = (r/rdiv)*rmul + r%rdiv.
// GEMM1: rdiv=1, rmul=1 (identity). GEMM2: rdiv=3, rmul=5 (skip d=3,4 slabs).
__global__ void __launch_bounds__(128)
gemm_kernel(const float* __restrict__ A, int lda, int rdiv, int rmul,
            const float* __restrict__ B, int N,
            float* __restrict__ C, size_t cSplit,
            int M, int kLen) {
    __shared__ float As[16][128];
    __shared__ float Bs[16][64];
    const int tid = threadIdx.x;
    const int tx = tid & 7;       // 8 col-groups
    const int ty = tid >> 3;      // 16 row-groups
    const int row0 = blockIdx.y * 128;
    const int col0 = blockIdx.x * 64;
    const int k0   = blockIdx.z * kLen;
    float acc[8][8];
    #pragma unroll
    for (int i = 0; i < 8; i++)
        #pragma unroll
        for (int j = 0; j < 8; j++) acc[i][j] = 0.f;

    for (int kt = 0; kt < kLen; kt += 16) {
        int kk = k0 + kt;
        #pragma unroll
        for (int j = 0; j < 4; j++) {
            int idx = tid + j*128;
            int r = idx >> 2, c = idx & 3;
            float4 v = make_float4(0.f, 0.f, 0.f, 0.f);
            int gr = row0 + r;
            if (gr < M) {
                int roff = (gr / rdiv) * rmul + (gr % rdiv);
                v = *(const float4*)(A + (size_t)roff*lda + kk + c*4);
            }
            As[c*4+0][r] = v.x; As[c*4+1][r] = v.y;
            As[c*4+2][r] = v.z; As[c*4+3][r] = v.w;
        }
        #pragma unroll
        for (int j = 0; j < 2; j++) {
            int idx = tid + j*128;
            int rb = idx >> 4, cb = idx & 15;
            *(float4*)&Bs[rb][cb*4] =
                *(const float4*)(B + (size_t)(kk + rb)*N + col0 + cb*4);
        }
        __syncthreads();
        #pragma unroll
        for (int k = 0; k < 16; k++) {
            float a[8], b[8];
            *(float4*)&a[0] = *(const float4*)&As[k][ty*4];
            *(float4*)&a[4] = *(const float4*)&As[k][64 + ty*4];
            *(float4*)&b[0] = *(const float4*)&Bs[k][tx*4];
            *(float4*)&b[4] = *(const float4*)&Bs[k][32 + tx*4];
            #pragma unroll
            for (int i = 0; i < 8; i++)
                #pragma unroll
                for (int j = 0; j < 8; j++)
                    acc[i][j] = fmaf(a[i], b[j], acc[i][j]);
        }
        __syncthreads();
    }
    float* Cb = C + (size_t)blockIdx.z * cSplit;
    #pragma unroll
    for (int i = 0; i < 8; i++) {
        int r = row0 + ((i < 4) ? (ty*4 + i) : (64 + ty*4 + (i-4)));
        if (r < M) {
            *(float4*)(Cb + (size_t)r*N + col0 + tx*4) =
                make_float4(acc[i][0], acc[i][1], acc[i][2], acc[i][3]);
            *(float4*)(Cb + (size_t)r*N + col0 + 32 + tx*4) =
                make_float4(acc[i][4], acc[i][5], acc[i][6], acc[i][7]);
        }
    }
}

// ---------------- 5: combine P over depth taps + bias + relu -> g_y --------
__global__ void combine_kernel(const float* __restrict__ b1a) {
    int bid = blockIdx.x;           // n*5 + d
    int n = bid / 5, d = bid % 5;
    __shared__ int mm[3];
    if (threadIdx.x < 3) {
        int t = d + threadIdx.x - 1;
        mm[threadIdx.x] = (t >= 0 && t < 5) ? g_map[n*5 + t] : -1;
    }
    __syncthreads();
    for (int idx = threadIdx.x; idx < 9*512; idx += blockDim.x) {
        int sp = idx >> 9, co = idx & 511;
        float acc = b1a[co];
        #pragma unroll
        for (int kd = 0; kd < 3; kd++) {
            int m = mm[kd];
            if (m >= 0)
                acc += g_P[((size_t)(m*9 + sp))*N1 + kd*512 + co];
        }
        g_y[(size_t)bid*4608 + idx] = fmaxf(acc, 0.f);
    }
}

// ---------------- 6: reduce split-K partials + bias/relu/max/FC ------------
__global__ void maxfc_kernel(const float* __restrict__ b1b,
                             const float* __restrict__ fcw,
                             const float* __restrict__ fcb,
                             float* __restrict__ out) {
    int n = blockIdx.x;             // 0..191
    __shared__ float z[256];
    int c = threadIdx.x;            // 256 threads
    float v = -3.4e38f;
    #pragma unroll
    for (int dd = 0; dd < 3; dd++) {
        float s = 0.f;
        #pragma unroll
        for (int zz = 0; zz < SPLIT2; zz++)
            s += g_C2p[(size_t)zz*M2*N2 + (size_t)(n*3 + dd)*N2 + c];
        v = fmaxf(v, s);
    }
    z[c] = fmaxf(v + b1b[c], 0.f);
    __syncthreads();
    int warp = threadIdx.x >> 5, lane = threadIdx.x & 31;
    for (int j = warp; j < NB; j += 8) {
        float s = 0.f;
        #pragma unroll
        for (int q = 0; q < 8; q++)
            s += z[lane + q*32] * fcw[j*256 + lane + q*32];
        #pragma unroll
        for (int off = 16; off; off >>= 1)
            s += __shfl_xor_sync(0xffffffffu, s, off);
        if (lane == 0) out[n*NB + j] = s + fcb[j];
    }
}

// ---------------- launch ----------------
extern "C" void kernel_launch(void* const* d_in, const int* in_sizes, int n_in,
                              void* d_out, int out_size) {
    const float* fmaps = (const float*)d_in[0];
    const float* boxes = (const float*)d_in[1];
    const int*   pids  = (const int*)d_in[2];
    const float* w1a   = (const float*)d_in[3];
    const float* b1a   = (const float*)d_in[4];
    const float* w1b   = (const float*)d_in[5];
    const float* b1b   = (const float*)d_in[6];
    const float* fcw   = (const float*)d_in[7];
    const float* fcb   = (const float*)d_in[8];
    float* out = (float*)d_out;

    float *pA1, *pB1, *pP, *pY, *pB2, *pC2p;
    cudaGetSymbolAddress((void**)&pA1,  g_A1);
    cudaGetSymbolAddress((void**)&pB1,  g_B1);
    cudaGetSymbolAddress((void**)&pP,   g_P);
    cudaGetSymbolAddress((void**)&pY,   g_y);
    cudaGetSymbolAddress((void**)&pB2,  g_B2);
    cudaGetSymbolAddress((void**)&pC2p, g_C2p);

    prep_map<<<1, 192>>>(pids);
    roi_kernel<<<NBOX, 256>>>(fmaps, boxes);
    t_w1a<<<dim3(27648/32, 512/32), dim3(32, 8)>>>(w1a);
    t_w1b<<<dim3(13824/32, 256/32), dim3(32, 8)>>>(w1b);
    im2col_kernel<<<M1, 256>>>();

    // G1: P[1728 x 1536] = A1[1728 x 9216] * B1[9216 x 1536]
    gemm_kernel<<<dim3(N1/64, (M1 + 127)/128, 1), 128>>>(
        pA1, K1, 1, 1, pB1, N1, pP, 0, M1, K1);

    combine_kernel<<<NBOX*5, 256>>>(b1a);

    // G2 split-K: C2p[z][576 x 256] = y-slab * B2 (deterministic partials)
    // logical row r = n*3+dd reads g_y slab (n*5+dd) via rdiv=3, rmul=5
    gemm_kernel<<<dim3(N2/64, (M2 + 127)/128, SPLIT2), 128>>>(
        pY, 4608, 3, 5, pB2, N2, pC2p, (size_t)M2*N2, M2, KLEN2);

    maxfc_kernel<<<NBOX, 256>>>(b1b, fcw, fcb, out);
}

// round 5
// speedup vs baseline: 1.9408x; 1.9408x over previous
#include <cuda_runtime.h>
#include <cuda_bf16.h>
#include <cstdint>

// ---------------- problem constants ----------------
#define F_    32
#define B_    6
#define C_    1024
#define HF    14
#define NB    27
#define T_    5
#define OUTP  3
#define SPAT  9
#define NBOX  (F_*B_)           // 192
#define K1    (C_*SPAT)         // 9216
#define N1    (3*512)           // 1536
#define M1    (NBOX*SPAT)       // 1728
#define M1P   1792              // padded to 14*128
#define K2    (512*27)          // 13824
#define M2    (NBOX*3)          // 576
#define N2    256
#define SPLIT2 12
#define KLEN2 (K2/SPLIT2)       // 1152

// ---------------- scratch (device globals; zero-init .bss) ----------------
__device__ int   g_map[NBOX*T_];
__device__ float g_roi[NBOX*C_*SPAT];
__device__ __align__(16) __nv_bfloat16 g_A0[(size_t)M1P*K1];  // im2col hi
__device__ __align__(16) __nv_bfloat16 g_A1[(size_t)M1P*K1];  // im2col lo
__device__ __align__(16) __nv_bfloat16 g_Bh[(size_t)N1*K1];   // w1a [n][k] hi
__device__ __align__(16) __nv_bfloat16 g_Bl[(size_t)N1*K1];   // w1a [n][k] lo
__device__ float g_P [(size_t)M1*N1];
__device__ float g_y [(size_t)NBOX*5*SPAT*512];
__device__ float g_B2[(size_t)K2*N2];
__device__ float g_C2p[(size_t)SPLIT2*M2*N2];

// ---------------- 0: temporal index + person matching ----------------
__global__ void prep_map(const int* __restrict__ person_ids) {
    int n = threadIdx.x;
    if (n >= NBOX) return;
    int f = n / B_, b = n % B_;
    int pid = person_ids[f*B_ + b];
    int start = max(f - T_/2, 0);
    int end   = min(start + T_ - 1, F_ - 1);
    for (int t = 0; t < T_; t++) {
        int g = (int)((float)start + (float)(t*(end-start)) / (float)(T_-1));
        int m = -1;
        for (int bp = 0; bp < B_; bp++)
            if (person_ids[g*B_ + bp] == pid) m = g*B_ + bp;
        g_map[n*T_ + t] = m;
    }
}

// ---------------- 1: ROI align ----------------
__global__ void roi_kernel(const float* __restrict__ fmaps,
                           const float* __restrict__ boxes) {
    int nb = blockIdx.x;
    int f  = nb / B_;
    __shared__ int   sy0[6], sy1[6], sx0[6], sx1[6];
    __shared__ float sly[6], slx[6];
    if (threadIdx.x < 12) {
        int  j   = threadIdx.x % 6;
        bool isx = threadIdx.x >= 6;
        float x1 = boxes[nb*4+0], y1 = boxes[nb*4+1];
        float x2 = boxes[nb*4+2], y2 = boxes[nb*4+3];
        float bw = fmaxf(x2 - x1, 1.0f) / (float)OUTP;
        float bh = fmaxf(y2 - y1, 1.0f) / (float)OUTP;
        float gj = (float)(j >> 1) + ((float)(j & 1) + 0.5f) * 0.5f;
        if (isx) {
            float xs  = x1 + bw * gj;
            float x0f = fminf(fmaxf(floorf(xs), 0.f), (float)(HF-1));
            float lx  = fminf(fmaxf(xs - x0f, 0.f), 1.f);
            int x0 = (int)x0f;
            sx0[j] = x0; sx1[j] = min(x0+1, HF-1); slx[j] = lx;
        } else {
            float ys  = y1 + bh * gj;
            float y0f = fminf(fmaxf(floorf(ys), 0.f), (float)(HF-1));
            float ly  = fminf(fmaxf(ys - y0f, 0.f), 1.f);
            int y0 = (int)y0f;
            sy0[j] = y0; sy1[j] = min(y0+1, HF-1); sly[j] = ly;
        }
    }
    __syncthreads();
    const float* base = fmaps + (size_t)f * C_ * HF * HF;
    for (int idx = threadIdx.x; idx < C_*SPAT; idx += blockDim.x) {
        int c = idx / SPAT, o = idx % SPAT;
        int oi = o / 3, oj = o % 3;
        const float* fm = base + (size_t)c * HF * HF;
        float acc = 0.f;
        #pragma unroll
        for (int s = 0; s < 4; s++) {
            int jy = oi*2 + (s >> 1);
            int jx = oj*2 + (s & 1);
            float ly = sly[jy], lx = slx[jx];
            int y0 = sy0[jy], y1i = sy1[jy], x0 = sx0[jx], x1i = sx1[jx];
            acc += fm[y0*HF + x0]  * (1.f-ly)*(1.f-lx)
                 + fm[y0*HF + x1i] * (1.f-ly)*lx
                 + fm[y1i*HF + x0] * ly*(1.f-lx)
                 + fm[y1i*HF + x1i]* ly*lx;
        }
        g_roi[(size_t)nb*C_*SPAT + idx] = acc * 0.25f;
    }
}

// ---------------- 2a: w1a -> bf16 split, [n=kd*512+co][k=ci*9+tap] ----------
__global__ void w1a_split(const float* __restrict__ w) {
    size_t t = (size_t)blockIdx.x * blockDim.x + threadIdx.x;
    if (t >= (size_t)N1 * K1) return;
    int n = (int)(t / K1), k = (int)(t % K1);
    int kd = n >> 9, co = n & 511;
    int ci = k / 9, tap = k % 9;
    float v = w[(size_t)co*27648 + ci*27 + kd*9 + tap];
    __nv_bfloat16 h = __float2bfloat16(v);
    __nv_bfloat16 l = __float2bfloat16(v - __bfloat162float(h));
    g_Bh[t] = h; g_Bl[t] = l;
}
// ---------------- 2b: w1b reorder (fp32, for SIMT GEMM2) ----------
__global__ void t_w1b(const float* __restrict__ w) {
    __shared__ float tile[32][33];
    int r0 = blockIdx.x * 32;
    int c0 = blockIdx.y * 32;
    int tx = threadIdx.x, ty = threadIdx.y;
    for (int yy = ty; yy < 32; yy += 8)
        tile[yy][tx] = w[(size_t)(c0+yy)*13824 + r0 + tx];
    __syncthreads();
    for (int yy = ty; yy < 32; yy += 8) {
        int rin = r0 + yy;
        int rout = (rin % 27)*512 + rin/27;
        g_B2[(size_t)rout*256 + c0 + tx] = tile[tx][yy];
    }
}

// ---------------- 3: im2col -> bf16 split ----------------
__global__ void im2col_split() {
    int bid = blockIdx.x;           // 0..1727 = slice*9 + sp
    int r = bid / 9, sp = bid % 9;
    int h = sp / 3, w = sp % 3;
    size_t dst = (size_t)bid * K1;
    const float* src = g_roi + (size_t)r * C_ * SPAT;
    for (int idx = threadIdx.x; idx < K1; idx += blockDim.x) {
        int ci = idx / 9, tap = idx % 9;
        int hi = h + tap/3 - 1, wi = w + tap%3 - 1;
        float v = 0.f;
        if (hi >= 0 && hi < 3 && wi >= 0 && wi < 3)
            v = src[ci*9 + hi*3 + wi];
        __nv_bfloat16 hh = __float2bfloat16(v);
        __nv_bfloat16 ll = __float2bfloat16(v - __bfloat162float(hh));
        g_A0[dst + idx] = hh; g_A1[dst + idx] = ll;
    }
}

// ---------------- 4: warp-MMA GEMM1: P = A * B^T (bf16 3-split, fp32 acc) --
// CTA tile 128x128, BK=32, 256 threads = 8 warps (4 M x 2 N), warp tile 32x64.
// SMEM tiles 128x32 bf16, 16B-chunk XOR swizzle: phys chunk = ck ^ (r & 3).
__device__ __forceinline__ uint32_t lds_b32(const __nv_bfloat16* s, int r, int k) {
    uint32_t byte = (uint32_t)r * 64u + ((((uint32_t)k >> 3) ^ ((uint32_t)r & 3)) << 4)
                  + (((uint32_t)k & 7) << 1);
    return *(const uint32_t*)((const char*)s + byte);
}
__device__ __forceinline__ void mma_bf16(float* d, const uint32_t* a,
                                         uint32_t b0, uint32_t b1) {
    asm volatile(
        "mma.sync.aligned.m16n8k16.row.col.f32.bf16.bf16.f32 "
        "{%0,%1,%2,%3}, {%4,%5,%6,%7}, {%8,%9}, {%0,%1,%2,%3};"
        : "+f"(d[0]), "+f"(d[1]), "+f"(d[2]), "+f"(d[3])
        : "r"(a[0]), "r"(a[1]), "r"(a[2]), "r"(a[3]), "r"(b0), "r"(b1));
}

__global__ void __launch_bounds__(256, 2)
gemm1_mma() {
    __shared__ __align__(16) __nv_bfloat16 sA0[128*32];
    __shared__ __align__(16) __nv_bfloat16 sA1[128*32];
    __shared__ __align__(16) __nv_bfloat16 sB0[128*32];
    __shared__ __align__(16) __nv_bfloat16 sB1[128*32];

    const int tid = threadIdx.x;
    const int lane = tid & 31, wid = tid >> 5;
    const int warp_m = wid & 3, warp_n = wid >> 2;
    const int g = lane >> 2, t = lane & 3;
    const int row0 = blockIdx.y * 128;
    const int col0 = blockIdx.x * 128;

    const uint4* A0g = (const uint4*)g_A0;
    const uint4* A1g = (const uint4*)g_A1;
    const uint4* B0g = (const uint4*)g_Bh;
    const uint4* B1g = (const uint4*)g_Bl;   // rows of 1152 uint4

    float acc[2][8][4];
    #pragma unroll
    for (int mt = 0; mt < 2; mt++)
        #pragma unroll
        for (int ni = 0; ni < 8; ni++)
            #pragma unroll
            for (int q = 0; q < 4; q++) acc[mt][ni][q] = 0.f;

    for (int it = 0; it < 288; it++) {
        // global loads: 512 chunks of 16B per array, 2 per thread
        uint4 va0[2], va1[2], vb0[2], vb1[2];
        #pragma unroll
        for (int j = 0; j < 2; j++) {
            int c = tid + j*256;
            int r = c >> 2, ck = c & 3;
            size_t ga = (size_t)(row0 + r)*1152 + it*4 + ck;
            size_t gb = (size_t)(col0 + r)*1152 + it*4 + ck;
            va0[j] = A0g[ga]; va1[j] = A1g[ga];
            vb0[j] = B0g[gb]; vb1[j] = B1g[gb];
        }
        __syncthreads();
        #pragma unroll
        for (int j = 0; j < 2; j++) {
            int c = tid + j*256;
            int r = c >> 2, ck = c & 3;
            uint32_t dst = (uint32_t)r*64u + (uint32_t)((ck ^ (r & 3)) << 4);
            *(uint4*)((char*)sA0 + dst) = va0[j];
            *(uint4*)((char*)sA1 + dst) = va1[j];
            *(uint4*)((char*)sB0 + dst) = vb0[j];
            *(uint4*)((char*)sB1 + dst) = vb1[j];
        }
        __syncthreads();

        #pragma unroll
        for (int ksub = 0; ksub < 2; ksub++) {
            const int k0 = ksub*16 + t*2;
            uint32_t ah[2][4], al[2][4];
            #pragma unroll
            for (int mt = 0; mt < 2; mt++) {
                int rb = warp_m*32 + mt*16;
                ah[mt][0] = lds_b32(sA0, rb + g,     k0);
                ah[mt][1] = lds_b32(sA0, rb + g + 8, k0);
                ah[mt][2] = lds_b32(sA0, rb + g,     k0 + 8);
                ah[mt][3] = lds_b32(sA0, rb + g + 8, k0 + 8);
                al[mt][0] = lds_b32(sA1, rb + g,     k0);
                al[mt][1] = lds_b32(sA1, rb + g + 8, k0);
                al[mt][2] = lds_b32(sA1, rb + g,     k0 + 8);
                al[mt][3] = lds_b32(sA1, rb + g + 8, k0 + 8);
            }
            #pragma unroll
            for (int ni = 0; ni < 8; ni++) {
                int nb = warp_n*64 + ni*8 + g;
                uint32_t bh0 = lds_b32(sB0, nb, k0);
                uint32_t bh1 = lds_b32(sB0, nb, k0 + 8);
                uint32_t bl0 = lds_b32(sB1, nb, k0);
                uint32_t bl1 = lds_b32(sB1, nb, k0 + 8);
                #pragma unroll
                for (int mt = 0; mt < 2; mt++) {
                    mma_bf16(acc[mt][ni], ah[mt], bh0, bh1);
                    mma_bf16(acc[mt][ni], ah[mt], bl0, bl1);
                    mma_bf16(acc[mt][ni], al[mt], bh0, bh1);
                }
            }
        }
    }

    // epilogue
    #pragma unroll
    for (int mt = 0; mt < 2; mt++) {
        int r_0 = row0 + warp_m*32 + mt*16 + g;
        int r_1 = r_0 + 8;
        #pragma unroll
        for (int ni = 0; ni < 8; ni++) {
            int cc = col0 + warp_n*64 + ni*8 + t*2;
            if (r_0 < M1)
                *(float2*)(g_P + (size_t)r_0*N1 + cc) =
                    make_float2(acc[mt][ni][0], acc[mt][ni][1]);
            if (r_1 < M1)
                *(float2*)(g_P + (size_t)r_1*N1 + cc) =
                    make_float2(acc[mt][ni][2], acc[mt][ni][3]);
        }
    }
}

// ---------------- SIMT GEMM (for GEMM2) ----------------
__global__ void __launch_bounds__(128)
gemm_kernel(const float* __restrict__ A, int lda, int rdiv, int rmul,
            const float* __restrict__ B, int N,
            float* __restrict__ C, size_t cSplit,
            int M, int kLen) {
    __shared__ float As[16][128];
    __shared__ float Bs[16][64];
    const int tid = threadIdx.x;
    const int tx = tid & 7;
    const int ty = tid >> 3;
    const int row0 = blockIdx.y * 128;
    const int col0 = blockIdx.x * 64;
    const int k0   = blockIdx.z * kLen;
    float acc[8][8];
    #pragma unroll
    for (int i = 0; i < 8; i++)
        #pragma unroll
        for (int j = 0; j < 8; j++) acc[i][j] = 0.f;

    for (int kt = 0; kt < kLen; kt += 16) {
        int kk = k0 + kt;
        #pragma unroll
        for (int j = 0; j < 4; j++) {
            int idx = tid + j*128;
            int r = idx >> 2, c = idx & 3;
            float4 v = make_float4(0.f, 0.f, 0.f, 0.f);
            int gr = row0 + r;
            if (gr < M) {
                int roff = (gr / rdiv) * rmul + (gr % rdiv);
                v = *(const float4*)(A + (size_t)roff*lda + kk + c*4);
            }
            As[c*4+0][r] = v.x; As[c*4+1][r] = v.y;
            As[c*4+2][r] = v.z; As[c*4+3][r] = v.w;
        }
        #pragma unroll
        for (int j = 0; j < 2; j++) {
            int idx = tid + j*128;
            int rb = idx >> 4, cb = idx & 15;
            *(float4*)&Bs[rb][cb*4] =
                *(const float4*)(B + (size_t)(kk + rb)*N + col0 + cb*4);
        }
        __syncthreads();
        #pragma unroll
        for (int k = 0; k < 16; k++) {
            float a[8], b[8];
            *(float4*)&a[0] = *(const float4*)&As[k][ty*4];
            *(float4*)&a[4] = *(const float4*)&As[k][64 + ty*4];
            *(float4*)&b[0] = *(const float4*)&Bs[k][tx*4];
            *(float4*)&b[4] = *(const float4*)&Bs[k][32 + tx*4];
            #pragma unroll
            for (int i = 0; i < 8; i++)
                #pragma unroll
                for (int j = 0; j < 8; j++)
                    acc[i][j] = fmaf(a[i], b[j], acc[i][j]);
        }
        __syncthreads();
    }
    float* Cb = C + (size_t)blockIdx.z * cSplit;
    #pragma unroll
    for (int i = 0; i < 8; i++) {
        int r = row0 + ((i < 4) ? (ty*4 + i) : (64 + ty*4 + (i-4)));
        if (r < M) {
            *(float4*)(Cb + (size_t)r*N + col0 + tx*4) =
                make_float4(acc[i][0], acc[i][1], acc[i][2], acc[i][3]);
            *(float4*)(Cb + (size_t)r*N + col0 + 32 + tx*4) =
                make_float4(acc[i][4], acc[i][5], acc[i][6], acc[i][7]);
        }
    }
}

// ---------------- 5: combine P over depth taps + bias + relu -> g_y --------
__global__ void combine_kernel(const float* __restrict__ b1a) {
    int bid = blockIdx.x;           // n*5 + d
    int n = bid / 5, d = bid % 5;
    __shared__ int mm[3];
    if (threadIdx.x < 3) {
        int t = d + threadIdx.x - 1;
        mm[threadIdx.x] = (t >= 0 && t < 5) ? g_map[n*5 + t] : -1;
    }
    __syncthreads();
    for (int idx = threadIdx.x; idx < 9*512; idx += blockDim.x) {
        int sp = idx >> 9, co = idx & 511;
        float acc = b1a[co];
        #pragma unroll
        for (int kd = 0; kd < 3; kd++) {
            int m = mm[kd];
            if (m >= 0)
                acc += g_P[((size_t)(m*9 + sp))*N1 + kd*512 + co];
        }
        g_y[(size_t)bid*4608 + idx] = fmaxf(acc, 0.f);
    }
}

// ---------------- 6: reduce split-K + bias/relu/max/FC ------------
__global__ void maxfc_kernel(const float* __restrict__ b1b,
                             const float* __restrict__ fcw,
                             const float* __restrict__ fcb,
                             float* __restrict__ out) {
    int n = blockIdx.x;
    __shared__ float z[256];
    int c = threadIdx.x;
    float v = -3.4e38f;
    #pragma unroll
    for (int dd = 0; dd < 3; dd++) {
        float s = 0.f;
        #pragma unroll
        for (int zz = 0; zz < SPLIT2; zz++)
            s += g_C2p[(size_t)zz*M2*N2 + (size_t)(n*3 + dd)*N2 + c];
        v = fmaxf(v, s);
    }
    z[c] = fmaxf(v + b1b[c], 0.f);
    __syncthreads();
    int warp = threadIdx.x >> 5, lane = threadIdx.x & 31;
    for (int j = warp; j < NB; j += 8) {
        float s = 0.f;
        #pragma unroll
        for (int q = 0; q < 8; q++)
            s += z[lane + q*32] * fcw[j*256 + lane + q*32];
        #pragma unroll
        for (int off = 16; off; off >>= 1)
            s += __shfl_xor_sync(0xffffffffu, s, off);
        if (lane == 0) out[n*NB + j] = s + fcb[j];
    }
}

// ---------------- launch ----------------
extern "C" void kernel_launch(void* const* d_in, const int* in_sizes, int n_in,
                              void* d_out, int out_size) {
    const float* fmaps = (const float*)d_in[0];
    const float* boxes = (const float*)d_in[1];
    const int*   pids  = (const int*)d_in[2];
    const float* w1a   = (const float*)d_in[3];
    const float* b1a   = (const float*)d_in[4];
    const float* w1b   = (const float*)d_in[5];
    const float* b1b   = (const float*)d_in[6];
    const float* fcw   = (const float*)d_in[7];
    const float* fcb   = (const float*)d_in[8];
    float* out = (float*)d_out;

    float *pY, *pB2, *pC2p;
    cudaGetSymbolAddress((void**)&pY,   g_y);
    cudaGetSymbolAddress((void**)&pB2,  g_B2);
    cudaGetSymbolAddress((void**)&pC2p, g_C2p);

    prep_map<<<1, 192>>>(pids);
    roi_kernel<<<NBOX, 256>>>(fmaps, boxes);
    {
        size_t tot = (size_t)N1 * K1;
        int blocks = (int)((tot + 255) / 256);
        w1a_split<<<blocks, 256>>>(w1a);
    }
    t_w1b<<<dim3(13824/32, 256/32), dim3(32, 8)>>>(w1b);
    im2col_split<<<M1, 256>>>();

    // G1 (warp-MMA bf16 3-split): P[1728 x 1536] = A * B^T
    gemm1_mma<<<dim3(N1/128, M1P/128), 256>>>();

    combine_kernel<<<NBOX*5, 256>>>(b1a);

    // G2 split-K SIMT: logical row r = n*3+dd reads g_y slab (n*5+dd)
    gemm_kernel<<<dim3(N2/64, (M2 + 127)/128, SPLIT2), 128>>>(
        pY, 4608, 3, 5, pB2, N2, pC2p, (size_t)M2*N2, M2, KLEN2);

    maxfc_kernel<<<NBOX, 256>>>(b1b, fcw, fcb, out);
}

// round 6
// speedup vs baseline: 2.4053x; 1.2393x over previous
#include <cuda_runtime.h>
#include <cuda_bf16.h>
#include <cstdint>

// ---------------- problem constants ----------------
#define F_    32
#define B_    6
#define C_    1024
#define HF    14
#define NB    27
#define T_    5
#define OUTP  3
#define SPAT  9
#define NBOX  (F_*B_)           // 192
#define K1    (C_*SPAT)         // 9216
#define N1    (3*512)           // 1536
#define M1    (NBOX*SPAT)       // 1728
#define M1P   1792
#define K2    (512*27)          // 13824
#define M2    (NBOX*3)          // 576
#define N2    256
#define SPLIT2 16
#define KIT2  27                // 864 elems per split = 27 BK32 iters

// ---------------- scratch ----------------
__device__ int   g_map[NBOX*T_];
__device__ float g_roi[NBOX*C_*SPAT];
__device__ __align__(16) __nv_bfloat16 g_A0[(size_t)M1P*K1];
__device__ __align__(16) __nv_bfloat16 g_A1[(size_t)M1P*K1];
__device__ __align__(16) __nv_bfloat16 g_Bh[(size_t)N1*K1];
__device__ __align__(16) __nv_bfloat16 g_Bl[(size_t)N1*K1];
__device__ float g_P [(size_t)M1*N1];
__device__ __align__(16) __nv_bfloat16 g_yh[(size_t)NBOX*5*4608];
__device__ __align__(16) __nv_bfloat16 g_yl[(size_t)NBOX*5*4608];
__device__ __align__(16) __nv_bfloat16 g_B2h[(size_t)N2*K2];
__device__ __align__(16) __nv_bfloat16 g_B2l[(size_t)N2*K2];
__device__ float g_C2p[(size_t)SPLIT2*M2*N2];

// ---------------- helpers ----------------
__device__ __forceinline__ uint32_t smem_u32(const void* p) {
    uint32_t a;
    asm("{ .reg .u64 t; cvta.to.shared.u64 t, %1; cvt.u32.u64 %0, t; }"
        : "=r"(a) : "l"(p));
    return a;
}
__device__ __forceinline__ void cpasync16(uint32_t dst, const void* src, uint32_t sz) {
    asm volatile("cp.async.cg.shared.global [%0], [%1], 16, %2;"
                 :: "r"(dst), "l"(__cvta_generic_to_global(src)), "r"(sz) : "memory");
}
#define CP_COMMIT() asm volatile("cp.async.commit_group;" ::: "memory")
#define CP_WAIT1()  asm volatile("cp.async.wait_group 1;" ::: "memory")
#define CP_WAIT0()  asm volatile("cp.async.wait_group 0;" ::: "memory")
#define LDSM4(rr, a) asm volatile( \
    "ldmatrix.sync.aligned.m8n8.x4.shared.b16 {%0,%1,%2,%3}, [%4];" \
    : "=r"((rr)[0]),"=r"((rr)[1]),"=r"((rr)[2]),"=r"((rr)[3]) : "r"(a))
__device__ __forceinline__ void mma_bf16(float* d, const uint32_t* a,
                                         uint32_t b0, uint32_t b1) {
    asm volatile(
        "mma.sync.aligned.m16n8k16.row.col.f32.bf16.bf16.f32 "
        "{%0,%1,%2,%3}, {%4,%5,%6,%7}, {%8,%9}, {%0,%1,%2,%3};"
        : "+f"(d[0]), "+f"(d[1]), "+f"(d[2]), "+f"(d[3])
        : "r"(a[0]), "r"(a[1]), "r"(a[2]), "r"(a[3]), "r"(b0), "r"(b1));
}
// swizzled byte offset within a 128x32 bf16 tile (64B rows, 16B chunks)
__device__ __forceinline__ uint32_t swz(int row, int ckl) {
    return (uint32_t)row*64u + (uint32_t)((ckl ^ (row & 3)) << 4);
}

// ---------------- 0: temporal index + person matching ----------------
__global__ void prep_map(const int* __restrict__ person_ids) {
    int n = threadIdx.x;
    if (n >= NBOX) return;
    int f = n / B_, b = n % B_;
    int pid = person_ids[f*B_ + b];
    int start = max(f - T_/2, 0);
    int end   = min(start + T_ - 1, F_ - 1);
    for (int t = 0; t < T_; t++) {
        int g = (int)((float)start + (float)(t*(end-start)) / (float)(T_-1));
        int m = -1;
        for (int bp = 0; bp < B_; bp++)
            if (person_ids[g*B_ + bp] == pid) m = g*B_ + bp;
        g_map[n*T_ + t] = m;
    }
}

// ---------------- 1: ROI align ----------------
__global__ void roi_kernel(const float* __restrict__ fmaps,
                           const float* __restrict__ boxes) {
    int nb = blockIdx.x;
    int f  = nb / B_;
    __shared__ int   sy0[6], sy1[6], sx0[6], sx1[6];
    __shared__ float sly[6], slx[6];
    if (threadIdx.x < 12) {
        int  j   = threadIdx.x % 6;
        bool isx = threadIdx.x >= 6;
        float x1 = boxes[nb*4+0], y1 = boxes[nb*4+1];
        float x2 = boxes[nb*4+2], y2 = boxes[nb*4+3];
        float bw = fmaxf(x2 - x1, 1.0f) / (float)OUTP;
        float bh = fmaxf(y2 - y1, 1.0f) / (float)OUTP;
        float gj = (float)(j >> 1) + ((float)(j & 1) + 0.5f) * 0.5f;
        if (isx) {
            float xs  = x1 + bw * gj;
            float x0f = fminf(fmaxf(floorf(xs), 0.f), (float)(HF-1));
            float lx  = fminf(fmaxf(xs - x0f, 0.f), 1.f);
            int x0 = (int)x0f;
            sx0[j] = x0; sx1[j] = min(x0+1, HF-1); slx[j] = lx;
        } else {
            float ys  = y1 + bh * gj;
            float y0f = fminf(fmaxf(floorf(ys), 0.f), (float)(HF-1));
            float ly  = fminf(fmaxf(ys - y0f, 0.f), 1.f);
            int y0 = (int)y0f;
            sy0[j] = y0; sy1[j] = min(y0+1, HF-1); sly[j] = ly;
        }
    }
    __syncthreads();
    const float* base = fmaps + (size_t)f * C_ * HF * HF;
    for (int idx = threadIdx.x; idx < C_*SPAT; idx += blockDim.x) {
        int c = idx / SPAT, o = idx % SPAT;
        int oi = o / 3, oj = o % 3;
        const float* fm = base + (size_t)c * HF * HF;
        float acc = 0.f;
        #pragma unroll
        for (int s = 0; s < 4; s++) {
            int jy = oi*2 + (s >> 1);
            int jx = oj*2 + (s & 1);
            float ly = sly[jy], lx = slx[jx];
            int y0 = sy0[jy], y1i = sy1[jy], x0 = sx0[jx], x1i = sx1[jx];
            acc += fm[y0*HF + x0]  * (1.f-ly)*(1.f-lx)
                 + fm[y0*HF + x1i] * (1.f-ly)*lx
                 + fm[y1i*HF + x0] * ly*(1.f-lx)
                 + fm[y1i*HF + x1i]* ly*lx;
        }
        g_roi[(size_t)nb*C_*SPAT + idx] = acc * 0.25f;
    }
}

// ---------------- 2a: w1a -> bf16 split, [n=kd*512+co][k=ci*9+tap] ----------
__global__ void w1a_split(const float* __restrict__ w) {
    size_t t = (size_t)blockIdx.x * blockDim.x + threadIdx.x;
    if (t >= (size_t)N1 * K1) return;
    int n = (int)(t / K1), k = (int)(t % K1);
    int kd = n >> 9, co = n & 511;
    int ci = k / 9, tap = k % 9;
    float v = w[(size_t)co*27648 + ci*27 + kd*9 + tap];
    __nv_bfloat16 h = __float2bfloat16(v);
    __nv_bfloat16 l = __float2bfloat16(v - __bfloat162float(h));
    g_Bh[t] = h; g_Bl[t] = l;
}
// ---------------- 2b: w1b -> bf16 split, [n=co2][k=(kd*9+sp)*512+ci] -------
__global__ void w1b_split(const float* __restrict__ w) {
    size_t t = (size_t)blockIdx.x * blockDim.x + threadIdx.x;
    if (t >= (size_t)N2 * K2) return;
    int n = (int)(t / K2), k = (int)(t % K2);
    int q = k >> 9, ci = k & 511;
    int kd = q / 9, sp = q % 9;
    float v = w[(size_t)n*13824 + ci*27 + kd*9 + sp];
    __nv_bfloat16 h = __float2bfloat16(v);
    __nv_bfloat16 l = __float2bfloat16(v - __bfloat162float(h));
    g_B2h[t] = h; g_B2l[t] = l;
}

// ---------------- 3: im2col -> bf16 split ----------------
__global__ void im2col_split() {
    int bid = blockIdx.x;           // 0..1727 = slice*9 + sp
    int r = bid / 9, sp = bid % 9;
    int h = sp / 3, w = sp % 3;
    size_t dst = (size_t)bid * K1;
    const float* src = g_roi + (size_t)r * C_ * SPAT;
    for (int idx = threadIdx.x; idx < K1; idx += blockDim.x) {
        int ci = idx / 9, tap = idx % 9;
        int hi = h + tap/3 - 1, wi = w + tap%3 - 1;
        float v = 0.f;
        if (hi >= 0 && hi < 3 && wi >= 0 && wi < 3)
            v = src[ci*9 + hi*3 + wi];
        __nv_bfloat16 hh = __float2bfloat16(v);
        __nv_bfloat16 ll = __float2bfloat16(v - __bfloat162float(hh));
        g_A0[dst + idx] = hh; g_A1[dst + idx] = ll;
    }
}

// ---------------- 4: pipelined warp-MMA GEMM (bf16 3-split, fp32 acc) ------
// CTA 128x128, BK=32, 2-stage cp.async pipeline, ldmatrix fragments.
// Stage layout (32KB): A0 @0, A1 @8192, B0 @16384, B1 @24576. Two stages.
__global__ void __launch_bounds__(256, 2)
gemm_mma(const __nv_bfloat16* __restrict__ A0, const __nv_bfloat16* __restrict__ A1,
         const __nv_bfloat16* __restrict__ B0, const __nv_bfloat16* __restrict__ B1,
         int kIters, size_t aStride, size_t bStride,
         int rdiv, int rmul, int Malloc, int Mstore,
         float* __restrict__ C, int ldc, size_t cSplit) {
    extern __shared__ char smem[];
    const uint32_t sb = smem_u32(smem);
    const int tid = threadIdx.x;
    const int lane = tid & 31, wid = tid >> 5;
    const int warp_m = wid & 3, warp_n = wid >> 2;
    const int g = lane >> 2, t4 = lane & 3;
    const int row0 = blockIdx.y * 128;
    const int col0 = blockIdx.x * 128;
    const int kStart = blockIdx.z * kIters * 32;

    // per-thread load geometry (2 chunks per array)
    int lr[2], lck[2], lroff[2];
    uint32_t lsz[2], ldst[2];
    #pragma unroll
    for (int j = 0; j < 2; j++) {
        int c = tid + j*256;
        lr[j] = c >> 2; lck[j] = c & 3;
        ldst[j] = swz(lr[j], lck[j]);
        int gr = row0 + lr[j];
        lroff[j] = (gr < Malloc) ? ((gr / rdiv) * rmul + (gr % rdiv)) : 0;
        lsz[j] = (gr < Malloc) ? 16u : 0u;
    }

    float acc[2][8][4];
    #pragma unroll
    for (int mt = 0; mt < 2; mt++)
        #pragma unroll
        for (int ni = 0; ni < 8; ni++)
            #pragma unroll
            for (int q = 0; q < 4; q++) acc[mt][ni][q] = 0.f;

    // prologue: stage 0
    {
        int kOff = kStart;
        #pragma unroll
        for (int j = 0; j < 2; j++) {
            size_t ka = (size_t)lroff[j]*aStride + kOff + lck[j]*8;
            size_t kb = (size_t)(col0 + lr[j])*bStride + kOff + lck[j]*8;
            cpasync16(sb +     0 + ldst[j], A0 + ka, lsz[j]);
            cpasync16(sb +  8192 + ldst[j], A1 + ka, lsz[j]);
            cpasync16(sb + 16384 + ldst[j], B0 + kb, 16u);
            cpasync16(sb + 24576 + ldst[j], B1 + kb, 16u);
        }
        CP_COMMIT();
    }

    for (int it = 0; it < kIters; it++) {
        if (it + 1 < kIters) {
            uint32_t nb = sb + (((it + 1) & 1) ? 32768u : 0u);
            int kOff = kStart + (it + 1) * 32;
            #pragma unroll
            for (int j = 0; j < 2; j++) {
                size_t ka = (size_t)lroff[j]*aStride + kOff + lck[j]*8;
                size_t kb = (size_t)(col0 + lr[j])*bStride + kOff + lck[j]*8;
                cpasync16(nb +     0 + ldst[j], A0 + ka, lsz[j]);
                cpasync16(nb +  8192 + ldst[j], A1 + ka, lsz[j]);
                cpasync16(nb + 16384 + ldst[j], B0 + kb, 16u);
                cpasync16(nb + 24576 + ldst[j], B1 + kb, 16u);
            }
            CP_COMMIT();
            CP_WAIT1();
        } else {
            CP_WAIT0();
        }
        __syncthreads();

        const uint32_t st = sb + ((it & 1) ? 32768u : 0u);
        #pragma unroll
        for (int ksub = 0; ksub < 2; ksub++) {
            const int ckl = ksub*2 + (lane >> 4);
            uint32_t ah[2][4], al[2][4];
            #pragma unroll
            for (int mt = 0; mt < 2; mt++) {
                int row = warp_m*32 + mt*16 + (lane & 15);
                uint32_t off = swz(row, ckl);
                LDSM4(ah[mt], st +    0 + off);
                LDSM4(al[mt], st + 8192 + off);
            }
            #pragma unroll
            for (int ni2 = 0; ni2 < 4; ni2++) {
                int row = warp_n*64 + ni2*16 + (lane & 15);
                uint32_t off = swz(row, ckl);
                uint32_t bh[4], bl[4];
                LDSM4(bh, st + 16384 + off);
                LDSM4(bl, st + 24576 + off);
                #pragma unroll
                for (int h = 0; h < 2; h++) {
                    const int ni = ni2*2 + h;
                    #pragma unroll
                    for (int mt = 0; mt < 2; mt++) {
                        mma_bf16(acc[mt][ni], ah[mt], bh[h], bh[2+h]);
                        mma_bf16(acc[mt][ni], ah[mt], bl[h], bl[2+h]);
                        mma_bf16(acc[mt][ni], al[mt], bh[h], bh[2+h]);
                    }
                }
            }
        }
        __syncthreads();
    }

    float* Cb = C + (size_t)blockIdx.z * cSplit;
    #pragma unroll
    for (int mt = 0; mt < 2; mt++) {
        int r_0 = row0 + warp_m*32 + mt*16 + g;
        int r_1 = r_0 + 8;
        #pragma unroll
        for (int ni = 0; ni < 8; ni++) {
            int cc = col0 + warp_n*64 + ni*8 + t4*2;
            if (r_0 < Mstore)
                *(float2*)(Cb + (size_t)r_0*ldc + cc) =
                    make_float2(acc[mt][ni][0], acc[mt][ni][1]);
            if (r_1 < Mstore)
                *(float2*)(Cb + (size_t)r_1*ldc + cc) =
                    make_float2(acc[mt][ni][2], acc[mt][ni][3]);
        }
    }
}

// ---------------- 5: combine P over depth taps + bias + relu -> y (bf16) ---
__global__ void combine_kernel(const float* __restrict__ b1a) {
    int bid = blockIdx.x;           // n*5 + d
    int n = bid / 5, d = bid % 5;
    __shared__ int mm[3];
    if (threadIdx.x < 3) {
        int t = d + threadIdx.x - 1;
        mm[threadIdx.x] = (t >= 0 && t < 5) ? g_map[n*5 + t] : -1;
    }
    __syncthreads();
    for (int idx = threadIdx.x; idx < 9*512; idx += blockDim.x) {
        int sp = idx >> 9, co = idx & 511;
        float acc = b1a[co];
        #pragma unroll
        for (int kd = 0; kd < 3; kd++) {
            int m = mm[kd];
            if (m >= 0)
                acc += g_P[((size_t)(m*9 + sp))*N1 + kd*512 + co];
        }
        acc = fmaxf(acc, 0.f);
        __nv_bfloat16 h = __float2bfloat16(acc);
        __nv_bfloat16 l = __float2bfloat16(acc - __bfloat162float(h));
        g_yh[(size_t)bid*4608 + idx] = h;
        g_yl[(size_t)bid*4608 + idx] = l;
    }
}

// ---------------- 6: reduce split-K + bias/relu/max/FC ------------
__global__ void maxfc_kernel(const float* __restrict__ b1b,
                             const float* __restrict__ fcw,
                             const float* __restrict__ fcb,
                             float* __restrict__ out) {
    int n = blockIdx.x;
    __shared__ float z[256];
    int c = threadIdx.x;
    float v = -3.4e38f;
    #pragma unroll
    for (int dd = 0; dd < 3; dd++) {
        float s = 0.f;
        #pragma unroll
        for (int zz = 0; zz < SPLIT2; zz++)
            s += g_C2p[(size_t)zz*M2*N2 + (size_t)(n*3 + dd)*N2 + c];
        v = fmaxf(v, s);
    }
    z[c] = fmaxf(v + b1b[c], 0.f);
    __syncthreads();
    int warp = threadIdx.x >> 5, lane = threadIdx.x & 31;
    for (int j = warp; j < NB; j += 8) {
        float s = 0.f;
        #pragma unroll
        for (int q = 0; q < 8; q++)
            s += z[lane + q*32] * fcw[j*256 + lane + q*32];
        #pragma unroll
        for (int off = 16; off; off >>= 1)
            s += __shfl_xor_sync(0xffffffffu, s, off);
        if (lane == 0) out[n*NB + j] = s + fcb[j];
    }
}

// ---------------- launch ----------------
extern "C" void kernel_launch(void* const* d_in, const int* in_sizes, int n_in,
                              void* d_out, int out_size) {
    const float* fmaps = (const float*)d_in[0];
    const float* boxes = (const float*)d_in[1];
    const int*   pids  = (const int*)d_in[2];
    const float* w1a   = (const float*)d_in[3];
    const float* b1a   = (const float*)d_in[4];
    const float* w1b   = (const float*)d_in[5];
    const float* b1b   = (const float*)d_in[6];
    const float* fcw   = (const float*)d_in[7];
    const float* fcb   = (const float*)d_in[8];
    float* out = (float*)d_out;

    __nv_bfloat16 *pA0, *pA1, *pBh, *pBl, *pYh, *pYl, *pB2h, *pB2l;
    float *pP, *pC2p;
    cudaGetSymbolAddress((void**)&pA0,  g_A0);
    cudaGetSymbolAddress((void**)&pA1,  g_A1);
    cudaGetSymbolAddress((void**)&pBh,  g_Bh);
    cudaGetSymbolAddress((void**)&pBl,  g_Bl);
    cudaGetSymbolAddress((void**)&pYh,  g_yh);
    cudaGetSymbolAddress((void**)&pYl,  g_yl);
    cudaGetSymbolAddress((void**)&pB2h, g_B2h);
    cudaGetSymbolAddress((void**)&pB2l, g_B2l);
    cudaGetSymbolAddress((void**)&pP,   g_P);
    cudaGetSymbolAddress((void**)&pC2p, g_C2p);

    cudaFuncSetAttribute(gemm_mma, cudaFuncAttributeMaxDynamicSharedMemorySize, 65536);

    prep_map<<<1, 192>>>(pids);
    roi_kernel<<<NBOX, 256>>>(fmaps, boxes);
    w1a_split<<<(int)(((size_t)N1*K1 + 255)/256), 256>>>(w1a);
    w1b_split<<<(int)(((size_t)N2*K2 + 255)/256), 256>>>(w1b);
    im2col_split<<<M1, 256>>>();

    // G1: P[1728x1536] = A[1728x9216] * B[1536x9216]^T
    gemm_mma<<<dim3(N1/128, M1P/128, 1), 256, 65536>>>(
        pA0, pA1, pBh, pBl, K1/32, K1, K1,
        1, 1, M1P, M1, pP, N1, 0);

    combine_kernel<<<NBOX*5, 256>>>(b1a);

    // G2 split-K: C2p[z][576x256] = y * B2^T, row remap (r/3)*5 + r%3
    gemm_mma<<<dim3(N2/128, (M2 + 127)/128, SPLIT2), 256, 65536>>>(
        pYh, pYl, pB2h, pB2l, KIT2, 4608, K2,
        3, 5, M2, M2, pC2p, N2, (size_t)M2*N2);

    maxfc_kernel<<<NBOX, 256>>>(b1b, fcw, fcb, out);
}

// round 7
// speedup vs baseline: 3.4943x; 1.4527x over previous
#include <cuda_runtime.h>
#include <cuda_fp16.h>
#include <cstdint>

// ---------------- problem constants ----------------
#define F_    32
#define B_    6
#define C_    1024
#define HF    14
#define NB    27
#define T_    5
#define OUTP  3
#define SPAT  9
#define NBOX  (F_*B_)           // 192
#define K1    (C_*SPAT)         // 9216
#define N1    (3*512)           // 1536
#define M1    (NBOX*SPAT)       // 1728 = 27*64
#define K2    (512*27)          // 13824
#define M2    (NBOX*3)          // 576 = 9*64
#define N2    256
#define SPLIT2 8
#define KIT2  54                // 13824/8/32

// ---------------- scratch ----------------
__device__ int   g_map[NBOX*T_];
__device__ float g_roi[NBOX*C_*SPAT];
__device__ __align__(16) __half g_A0[(size_t)M1*K1];   // im2col hi
__device__ __align__(16) __half g_A1[(size_t)M1*K1];   // im2col lo
__device__ __align__(16) __half g_B1[(size_t)N1*K1];   // w1a [n][k] fp16
__device__ float g_P [(size_t)M1*N1];
__device__ __align__(16) __half g_yh[(size_t)NBOX*5*4608];
__device__ __align__(16) __half g_yl[(size_t)NBOX*5*4608];
__device__ __align__(16) __half g_B2[(size_t)N2*K2];   // w1b [n][k] fp16
__device__ float g_C2p[(size_t)SPLIT2*M2*N2];

// ---------------- helpers ----------------
__device__ __forceinline__ void cpasync16(uint32_t dst, const void* src) {
    asm volatile("cp.async.cg.shared.global [%0], [%1], 16;"
                 :: "r"(dst), "l"(__cvta_generic_to_global(src)) : "memory");
}
__device__ __forceinline__ uint32_t smem_u32(const void* p) {
    uint32_t a;
    asm("{ .reg .u64 t; cvta.to.shared.u64 t, %1; cvt.u32.u64 %0, t; }"
        : "=r"(a) : "l"(p));
    return a;
}
#define CP_COMMIT() asm volatile("cp.async.commit_group;" ::: "memory")
#define CP_WAIT2()  asm volatile("cp.async.wait_group 2;" ::: "memory")
#define CP_WAIT1()  asm volatile("cp.async.wait_group 1;" ::: "memory")
#define CP_WAIT0()  asm volatile("cp.async.wait_group 0;" ::: "memory")
#define LDSM4(rr, a) asm volatile( \
    "ldmatrix.sync.aligned.m8n8.x4.shared.b16 {%0,%1,%2,%3}, [%4];" \
    : "=r"((rr)[0]),"=r"((rr)[1]),"=r"((rr)[2]),"=r"((rr)[3]) : "r"(a))
__device__ __forceinline__ void mma_f16(float* d, const uint32_t* a,
                                        uint32_t b0, uint32_t b1) {
    asm volatile(
        "mma.sync.aligned.m16n8k16.row.col.f32.f16.f16.f32 "
        "{%0,%1,%2,%3}, {%4,%5,%6,%7}, {%8,%9}, {%0,%1,%2,%3};"
        : "+f"(d[0]), "+f"(d[1]), "+f"(d[2]), "+f"(d[3])
        : "r"(a[0]), "r"(a[1]), "r"(a[2]), "r"(a[3]), "r"(b0), "r"(b1));
}
// swizzled byte offset within rows x 32 fp16 tile (64B rows, 16B chunks)
__device__ __forceinline__ uint32_t swz(int row, int ckl) {
    return (uint32_t)row*64u + (uint32_t)((ckl ^ (row & 3)) << 4);
}

// ---------------- 0: temporal index + person matching ----------------
__global__ void prep_map(const int* __restrict__ person_ids) {
    int n = threadIdx.x;
    if (n >= NBOX) return;
    int f = n / B_, b = n % B_;
    int pid = person_ids[f*B_ + b];
    int start = max(f - T_/2, 0);
    int end   = min(start + T_ - 1, F_ - 1);
    for (int t = 0; t < T_; t++) {
        int g = (int)((float)start + (float)(t*(end-start)) / (float)(T_-1));
        int m = -1;
        for (int bp = 0; bp < B_; bp++)
            if (person_ids[g*B_ + bp] == pid) m = g*B_ + bp;
        g_map[n*T_ + t] = m;
    }
}

// ---------------- 1: ROI align ----------------
__global__ void roi_kernel(const float* __restrict__ fmaps,
                           const float* __restrict__ boxes) {
    int nb = blockIdx.x;
    int f  = nb / B_;
    __shared__ int   sy0[6], sy1[6], sx0[6], sx1[6];
    __shared__ float sly[6], slx[6];
    if (threadIdx.x < 12) {
        int  j   = threadIdx.x % 6;
        bool isx = threadIdx.x >= 6;
        float x1 = boxes[nb*4+0], y1 = boxes[nb*4+1];
        float x2 = boxes[nb*4+2], y2 = boxes[nb*4+3];
        float bw = fmaxf(x2 - x1, 1.0f) / (float)OUTP;
        float bh = fmaxf(y2 - y1, 1.0f) / (float)OUTP;
        float gj = (float)(j >> 1) + ((float)(j & 1) + 0.5f) * 0.5f;
        if (isx) {
            float xs  = x1 + bw * gj;
            float x0f = fminf(fmaxf(floorf(xs), 0.f), (float)(HF-1));
            float lx  = fminf(fmaxf(xs - x0f, 0.f), 1.f);
            int x0 = (int)x0f;
            sx0[j] = x0; sx1[j] = min(x0+1, HF-1); slx[j] = lx;
        } else {
            float ys  = y1 + bh * gj;
            float y0f = fminf(fmaxf(floorf(ys), 0.f), (float)(HF-1));
            float ly  = fminf(fmaxf(ys - y0f, 0.f), 1.f);
            int y0 = (int)y0f;
            sy0[j] = y0; sy1[j] = min(y0+1, HF-1); sly[j] = ly;
        }
    }
    __syncthreads();
    const float* base = fmaps + (size_t)f * C_ * HF * HF;
    for (int idx = threadIdx.x; idx < C_*SPAT; idx += blockDim.x) {
        int c = idx / SPAT, o = idx % SPAT;
        int oi = o / 3, oj = o % 3;
        const float* fm = base + (size_t)c * HF * HF;
        float acc = 0.f;
        #pragma unroll
        for (int s = 0; s < 4; s++) {
            int jy = oi*2 + (s >> 1);
            int jx = oj*2 + (s & 1);
            float ly = sly[jy], lx = slx[jx];
            int y0 = sy0[jy], y1i = sy1[jy], x0 = sx0[jx], x1i = sx1[jx];
            acc += fm[y0*HF + x0]  * (1.f-ly)*(1.f-lx)
                 + fm[y0*HF + x1i] * (1.f-ly)*lx
                 + fm[y1i*HF + x0] * ly*(1.f-lx)
                 + fm[y1i*HF + x1i]* ly*lx;
        }
        g_roi[(size_t)nb*C_*SPAT + idx] = acc * 0.25f;
    }
}

// ---------------- 2a: w1a -> fp16, [n=kd*512+co][k=ci*9+tap] ----------
__global__ void w1a_prep(const float* __restrict__ w) {
    size_t t = (size_t)blockIdx.x * blockDim.x + threadIdx.x;
    if (t >= (size_t)N1 * K1) return;
    int n = (int)(t / K1), k = (int)(t % K1);
    int kd = n >> 9, co = n & 511;
    int ci = k / 9, tap = k % 9;
    g_B1[t] = __float2half(w[(size_t)co*27648 + ci*27 + kd*9 + tap]);
}
// ---------------- 2b: w1b -> fp16, [n=co2][k=(kd*9+sp)*512+ci] -------
__global__ void w1b_prep(const float* __restrict__ w) {
    size_t t = (size_t)blockIdx.x * blockDim.x + threadIdx.x;
    if (t >= (size_t)N2 * K2) return;
    int n = (int)(t / K2), k = (int)(t % K2);
    int q = k >> 9, ci = k & 511;
    int kd = q / 9, sp = q % 9;
    g_B2[t] = __float2half(w[(size_t)n*13824 + ci*27 + kd*9 + sp]);
}

// ---------------- 3: im2col -> fp16 2-split ----------------
__global__ void im2col_split() {
    int bid = blockIdx.x;           // 0..1727 = slice*9 + sp
    int r = bid / 9, sp = bid % 9;
    int h = sp / 3, w = sp % 3;
    size_t dst = (size_t)bid * K1;
    const float* src = g_roi + (size_t)r * C_ * SPAT;
    for (int idx = threadIdx.x; idx < K1; idx += blockDim.x) {
        int ci = idx / 9, tap = idx % 9;
        int hi = h + tap/3 - 1, wi = w + tap%3 - 1;
        float v = 0.f;
        if (hi >= 0 && hi < 3 && wi >= 0 && wi < 3)
            v = src[ci*9 + hi*3 + wi];
        __half hh = __float2half(v);
        g_A0[dst + idx] = hh;
        g_A1[dst + idx] = __float2half(v - __half2float(hh));
    }
}

// ---------------- 4: pipelined warp-MMA GEMM (fp16 2-term, fp32 acc) ------
// CTA tile 64x128, BK=32, 3-stage cp.async, 256 thr = 8 warps (2M x 4N).
// Stage (16KB): A0 @0 (4KB), A1 @4096, B @8192 (8KB). Exact tiling, no bounds.
__global__ void __launch_bounds__(256, 2)
gemm_mma(const __half* __restrict__ A0, const __half* __restrict__ A1,
         const __half* __restrict__ B0,
         int kIters, size_t aStride, size_t bStride,
         int rdiv, int rmul,
         float* __restrict__ C, int ldc, size_t cSplit) {
    extern __shared__ char smem[];
    const uint32_t sb = smem_u32(smem);
    const int tid = threadIdx.x;
    const int lane = tid & 31, wid = tid >> 5;
    const int warp_m = wid & 1, warp_n = wid >> 1;
    const int g = lane >> 2, t4 = lane & 3;
    const int row0 = blockIdx.y * 64;
    const int col0 = blockIdx.x * 128;
    const int kStart = blockIdx.z * kIters * 32;

    // load geometry
    const int rA = tid >> 2, ckA = tid & 3;           // 64 rows x 4 chunks
    const uint32_t dstA = swz(rA, ckA);
    const int grA = row0 + rA;
    const size_t roffA = (size_t)((grA / rdiv) * rmul + (grA % rdiv)) * aStride
                       + (size_t)(ckA * 8);
    const int rB0 = tid >> 1 >> 1, ckB0 = tid & 3;    // chunk c = tid
    const int rB1 = (tid + 256) >> 2, ckB1 = tid & 3; // chunk c = tid+256
    const uint32_t dstB0 = swz(rB0, ckB0);
    const uint32_t dstB1 = swz(rB1, ckB1);
    const size_t goffB0 = (size_t)(col0 + rB0) * bStride + (size_t)(ckB0 * 8);
    const size_t goffB1 = (size_t)(col0 + rB1) * bStride + (size_t)(ckB1 * 8);

    float acc[2][4][4];
    #pragma unroll
    for (int mt = 0; mt < 2; mt++)
        #pragma unroll
        for (int ni = 0; ni < 4; ni++)
            #pragma unroll
            for (int q = 0; q < 4; q++) acc[mt][ni][q] = 0.f;

    // prologue: stages 0,1
    #pragma unroll
    for (int p = 0; p < 2; p++) {
        uint32_t st = sb + p * 16384u;
        int kOff = kStart + p * 32;
        cpasync16(st +    0 + dstA, A0 + roffA + kOff);
        cpasync16(st + 4096 + dstA, A1 + roffA + kOff);
        cpasync16(st + 8192 + dstB0, B0 + goffB0 + kOff);
        cpasync16(st + 8192 + dstB1, B0 + goffB1 + kOff);
        CP_COMMIT();
    }

    int sIdx = 0;
    for (int it = 0; it < kIters; it++) {
        if (it + 2 < kIters) {
            int pIdx = sIdx + 2; if (pIdx >= 3) pIdx -= 3;
            uint32_t st = sb + pIdx * 16384u;
            int kOff = kStart + (it + 2) * 32;
            cpasync16(st +    0 + dstA, A0 + roffA + kOff);
            cpasync16(st + 4096 + dstA, A1 + roffA + kOff);
            cpasync16(st + 8192 + dstB0, B0 + goffB0 + kOff);
            cpasync16(st + 8192 + dstB1, B0 + goffB1 + kOff);
            CP_COMMIT();
            CP_WAIT2();
        } else if (it + 1 < kIters) {
            CP_WAIT1();
        } else {
            CP_WAIT0();
        }
        __syncthreads();

        const uint32_t st = sb + sIdx * 16384u;
        #pragma unroll
        for (int ksub = 0; ksub < 2; ksub++) {
            const int ckl = ksub*2 + (lane >> 4);
            uint32_t ah[2][4], al[2][4];
            #pragma unroll
            for (int mt = 0; mt < 2; mt++) {
                int row = warp_m*32 + mt*16 + (lane & 15);
                uint32_t off = swz(row, ckl);
                LDSM4(ah[mt], st +    0 + off);
                LDSM4(al[mt], st + 4096 + off);
            }
            #pragma unroll
            for (int ni2 = 0; ni2 < 2; ni2++) {
                int row = warp_n*32 + ni2*16 + (lane & 15);
                uint32_t bh[4];
                LDSM4(bh, st + 8192 + swz(row, ckl));
                #pragma unroll
                for (int h = 0; h < 2; h++) {
                    const int ni = ni2*2 + h;
                    #pragma unroll
                    for (int mt = 0; mt < 2; mt++) {
                        mma_f16(acc[mt][ni], ah[mt], bh[h], bh[2+h]);
                        mma_f16(acc[mt][ni], al[mt], bh[h], bh[2+h]);
                    }
                }
            }
        }
        __syncthreads();
        if (++sIdx == 3) sIdx = 0;
    }

    float* Cb = C + (size_t)blockIdx.z * cSplit;
    #pragma unroll
    for (int mt = 0; mt < 2; mt++) {
        int r_0 = row0 + warp_m*32 + mt*16 + g;
        int r_1 = r_0 + 8;
        #pragma unroll
        for (int ni = 0; ni < 4; ni++) {
            int cc = col0 + warp_n*32 + ni*8 + t4*2;
            *(float2*)(Cb + (size_t)r_0*ldc + cc) =
                make_float2(acc[mt][ni][0], acc[mt][ni][1]);
            *(float2*)(Cb + (size_t)r_1*ldc + cc) =
                make_float2(acc[mt][ni][2], acc[mt][ni][3]);
        }
    }
}

// ---------------- 5: combine P over depth taps + bias + relu -> y (fp16) ---
__global__ void combine_kernel(const float* __restrict__ b1a) {
    int bid = blockIdx.x;           // n*5 + d
    int n = bid / 5, d = bid % 5;
    __shared__ int mm[3];
    if (threadIdx.x < 3) {
        int t = d + threadIdx.x - 1;
        mm[threadIdx.x] = (t >= 0 && t < 5) ? g_map[n*5 + t] : -1;
    }
    __syncthreads();
    for (int idx = threadIdx.x; idx < 9*512; idx += blockDim.x) {
        int sp = idx >> 9, co = idx & 511;
        float acc = b1a[co];
        #pragma unroll
        for (int kd = 0; kd < 3; kd++) {
            int m = mm[kd];
            if (m >= 0)
                acc += g_P[((size_t)(m*9 + sp))*N1 + kd*512 + co];
        }
        acc = fmaxf(acc, 0.f);
        __half h = __float2half(acc);
        g_yh[(size_t)bid*4608 + idx] = h;
        g_yl[(size_t)bid*4608 + idx] = __float2half(acc - __half2float(h));
    }
}

// ---------------- 6: reduce split-K + bias/relu/max/FC ------------
__global__ void maxfc_kernel(const float* __restrict__ b1b,
                             const float* __restrict__ fcw,
                             const float* __restrict__ fcb,
                             float* __restrict__ out) {
    int n = blockIdx.x;
    __shared__ float z[256];
    int c = threadIdx.x;
    float v = -3.4e38f;
    #pragma unroll
    for (int dd = 0; dd < 3; dd++) {
        float s = 0.f;
        #pragma unroll
        for (int zz = 0; zz < SPLIT2; zz++)
            s += g_C2p[(size_t)zz*M2*N2 + (size_t)(n*3 + dd)*N2 + c];
        v = fmaxf(v, s);
    }
    z[c] = fmaxf(v + b1b[c], 0.f);
    __syncthreads();
    int warp = threadIdx.x >> 5, lane = threadIdx.x & 31;
    for (int j = warp; j < NB; j += 8) {
        float s = 0.f;
        #pragma unroll
        for (int q = 0; q < 8; q++)
            s += z[lane + q*32] * fcw[j*256 + lane + q*32];
        #pragma unroll
        for (int off = 16; off; off >>= 1)
            s += __shfl_xor_sync(0xffffffffu, s, off);
        if (lane == 0) out[n*NB + j] = s + fcb[j];
    }
}

// ---------------- launch ----------------
extern "C" void kernel_launch(void* const* d_in, const int* in_sizes, int n_in,
                              void* d_out, int out_size) {
    const float* fmaps = (const float*)d_in[0];
    const float* boxes = (const float*)d_in[1];
    const int*   pids  = (const int*)d_in[2];
    const float* w1a   = (const float*)d_in[3];
    const float* b1a   = (const float*)d_in[4];
    const float* w1b   = (const float*)d_in[5];
    const float* b1b   = (const float*)d_in[6];
    const float* fcw   = (const float*)d_in[7];
    const float* fcb   = (const float*)d_in[8];
    float* out = (float*)d_out;

    __half *pA0, *pA1, *pB1, *pYh, *pYl, *pB2;
    float *pP, *pC2p;
    cudaGetSymbolAddress((void**)&pA0, g_A0);
    cudaGetSymbolAddress((void**)&pA1, g_A1);
    cudaGetSymbolAddress((void**)&pB1, g_B1);
    cudaGetSymbolAddress((void**)&pYh, g_yh);
    cudaGetSymbolAddress((void**)&pYl, g_yl);
    cudaGetSymbolAddress((void**)&pB2, g_B2);
    cudaGetSymbolAddress((void**)&pP,  g_P);
    cudaGetSymbolAddress((void**)&pC2p, g_C2p);

    cudaFuncSetAttribute(gemm_mma, cudaFuncAttributeMaxDynamicSharedMemorySize, 49152);

    prep_map<<<1, 192>>>(pids);
    roi_kernel<<<NBOX, 256>>>(fmaps, boxes);
    w1a_prep<<<(int)(((size_t)N1*K1 + 255)/256), 256>>>(w1a);
    w1b_prep<<<(int)(((size_t)N2*K2 + 255)/256), 256>>>(w1b);
    im2col_split<<<M1, 256>>>();

    // G1: P[1728x1536] = A[1728x9216] * B[1536x9216]^T  (324 CTAs)
    gemm_mma<<<dim3(N1/128, M1/64, 1), 256, 49152>>>(
        pA0, pA1, pB1, K1/32, K1, K1, 1, 1, pP, N1, 0);

    combine_kernel<<<NBOX*5, 256>>>(b1a);

    // G2 split-K=8: C2p[z][576x256] = y * B2^T, row remap (r/3)*5 + r%3
    gemm_mma<<<dim3(N2/128, M2/64, SPLIT2), 256, 49152>>>(
        pYh, pYl, pB2, KIT2, 4608, K2, 3, 5, pC2p, N2, (size_t)M2*N2);

    maxfc_kernel<<<NBOX, 256>>>(b1b, fcw, fcb, out);
}

// round 8
// speedup vs baseline: 4.7858x; 1.3696x over previous
#include <cuda_runtime.h>
#include <cuda_fp16.h>
#include <cstdint>

// ---------------- problem constants ----------------
#define F_    32
#define B_    6
#define C_    1024
#define HF    14
#define NB    27
#define T_    5
#define OUTP  3
#define SPAT  9
#define NBOX  (F_*B_)           // 192
#define K1    (C_*SPAT)         // 9216
#define N1    (3*512)           // 1536
#define M1    (NBOX*SPAT)       // 1728 = 27*64
#define K2    (512*27)          // 13824
#define M2    (NBOX*3)          // 576 = 9*64
#define N2    256
#define SPLIT2 8
#define KIT2  54                // 13824/8/32

// ---------------- scratch ----------------
__device__ int   g_map[NBOX*T_];
__device__ float g_roi[NBOX*C_*SPAT];
__device__ __align__(16) __half g_A0[(size_t)M1*K1];   // im2col fp16
__device__ __align__(16) __half g_B1[(size_t)N1*K1];   // w1a [n][k] fp16
__device__ float g_P [(size_t)M1*N1];
__device__ __align__(16) __half g_yh[(size_t)NBOX*5*4608];
__device__ __align__(16) __half g_B2[(size_t)N2*K2];   // w1b [n][k] fp16
__device__ float g_C2p[(size_t)SPLIT2*M2*N2];

// ---------------- helpers ----------------
__device__ __forceinline__ void cpasync16(uint32_t dst, const void* src) {
    asm volatile("cp.async.cg.shared.global [%0], [%1], 16;"
                 :: "r"(dst), "l"(__cvta_generic_to_global(src)) : "memory");
}
__device__ __forceinline__ uint32_t smem_u32(const void* p) {
    uint32_t a;
    asm("{ .reg .u64 t; cvta.to.shared.u64 t, %1; cvt.u32.u64 %0, t; }"
        : "=r"(a) : "l"(p));
    return a;
}
#define CP_COMMIT() asm volatile("cp.async.commit_group;" ::: "memory")
#define CP_WAIT2()  asm volatile("cp.async.wait_group 2;" ::: "memory")
#define CP_WAIT1()  asm volatile("cp.async.wait_group 1;" ::: "memory")
#define CP_WAIT0()  asm volatile("cp.async.wait_group 0;" ::: "memory")
#define LDSM4(rr, a) asm volatile( \
    "ldmatrix.sync.aligned.m8n8.x4.shared.b16 {%0,%1,%2,%3}, [%4];" \
    : "=r"((rr)[0]),"=r"((rr)[1]),"=r"((rr)[2]),"=r"((rr)[3]) : "r"(a))
__device__ __forceinline__ void mma_f16(float* d, const uint32_t* a,
                                        uint32_t b0, uint32_t b1) {
    asm volatile(
        "mma.sync.aligned.m16n8k16.row.col.f32.f16.f16.f32 "
        "{%0,%1,%2,%3}, {%4,%5,%6,%7}, {%8,%9}, {%0,%1,%2,%3};"
        : "+f"(d[0]), "+f"(d[1]), "+f"(d[2]), "+f"(d[3])
        : "r"(a[0]), "r"(a[1]), "r"(a[2]), "r"(a[3]), "r"(b0), "r"(b1));
}
// swizzled byte offset within rows x 32 fp16 tile (64B rows, 16B chunks)
__device__ __forceinline__ uint32_t swz(int row, int ckl) {
    return (uint32_t)row*64u + (uint32_t)((ckl ^ (row & 3)) << 4);
}

// ---------------- 0: temporal index + person matching ----------------
__global__ void prep_map(const int* __restrict__ person_ids) {
    int n = threadIdx.x;
    if (n >= NBOX) return;
    int f = n / B_, b = n % B_;
    int pid = person_ids[f*B_ + b];
    int start = max(f - T_/2, 0);
    int end   = min(start + T_ - 1, F_ - 1);
    for (int t = 0; t < T_; t++) {
        int g = (int)((float)start + (float)(t*(end-start)) / (float)(T_-1));
        int m = -1;
        for (int bp = 0; bp < B_; bp++)
            if (person_ids[g*B_ + bp] == pid) m = g*B_ + bp;
        g_map[n*T_ + t] = m;
    }
}

// ---------------- 1: ROI align ----------------
__global__ void roi_kernel(const float* __restrict__ fmaps,
                           const float* __restrict__ boxes) {
    int nb = blockIdx.x;
    int f  = nb / B_;
    __shared__ int   sy0[6], sy1[6], sx0[6], sx1[6];
    __shared__ float sly[6], slx[6];
    if (threadIdx.x < 12) {
        int  j   = threadIdx.x % 6;
        bool isx = threadIdx.x >= 6;
        float x1 = boxes[nb*4+0], y1 = boxes[nb*4+1];
        float x2 = boxes[nb*4+2], y2 = boxes[nb*4+3];
        float bw = fmaxf(x2 - x1, 1.0f) / (float)OUTP;
        float bh = fmaxf(y2 - y1, 1.0f) / (float)OUTP;
        float gj = (float)(j >> 1) + ((float)(j & 1) + 0.5f) * 0.5f;
        if (isx) {
            float xs  = x1 + bw * gj;
            float x0f = fminf(fmaxf(floorf(xs), 0.f), (float)(HF-1));
            float lx  = fminf(fmaxf(xs - x0f, 0.f), 1.f);
            int x0 = (int)x0f;
            sx0[j] = x0; sx1[j] = min(x0+1, HF-1); slx[j] = lx;
        } else {
            float ys  = y1 + bh * gj;
            float y0f = fminf(fmaxf(floorf(ys), 0.f), (float)(HF-1));
            float ly  = fminf(fmaxf(ys - y0f, 0.f), 1.f);
            int y0 = (int)y0f;
            sy0[j] = y0; sy1[j] = min(y0+1, HF-1); sly[j] = ly;
        }
    }
    __syncthreads();
    const float* base = fmaps + (size_t)f * C_ * HF * HF;
    for (int idx = threadIdx.x; idx < C_*SPAT; idx += blockDim.x) {
        int c = idx / SPAT, o = idx % SPAT;
        int oi = o / 3, oj = o % 3;
        const float* fm = base + (size_t)c * HF * HF;
        float acc = 0.f;
        #pragma unroll
        for (int s = 0; s < 4; s++) {
            int jy = oi*2 + (s >> 1);
            int jx = oj*2 + (s & 1);
            float ly = sly[jy], lx = slx[jx];
            int y0 = sy0[jy], y1i = sy1[jy], x0 = sx0[jx], x1i = sx1[jx];
            acc += fm[y0*HF + x0]  * (1.f-ly)*(1.f-lx)
                 + fm[y0*HF + x1i] * (1.f-ly)*lx
                 + fm[y1i*HF + x0] * ly*(1.f-lx)
                 + fm[y1i*HF + x1i]* ly*lx;
        }
        g_roi[(size_t)nb*C_*SPAT + idx] = acc * 0.25f;
    }
}

// ---------------- 2a: w1a -> fp16, [n=kd*512+co][k=ci*9+tap] ----------
__global__ void w1a_prep(const float* __restrict__ w) {
    size_t t = (size_t)blockIdx.x * blockDim.x + threadIdx.x;
    if (t >= (size_t)N1 * K1) return;
    int n = (int)(t / K1), k = (int)(t % K1);
    int kd = n >> 9, co = n & 511;
    int ci = k / 9, tap = k % 9;
    g_B1[t] = __float2half(w[(size_t)co*27648 + ci*27 + kd*9 + tap]);
}
// ---------------- 2b: w1b -> fp16, [n=co2][k=(kd*9+sp)*512+ci] -------
__global__ void w1b_prep(const float* __restrict__ w) {
    size_t t = (size_t)blockIdx.x * blockDim.x + threadIdx.x;
    if (t >= (size_t)N2 * K2) return;
    int n = (int)(t / K2), k = (int)(t % K2);
    int q = k >> 9, ci = k & 511;
    int kd = q / 9, sp = q % 9;
    g_B2[t] = __float2half(w[(size_t)n*13824 + ci*27 + kd*9 + sp]);
}

// ---------------- 3: im2col -> fp16 ----------------
__global__ void im2col_f16() {
    int bid = blockIdx.x;           // 0..1727 = slice*9 + sp
    int r = bid / 9, sp = bid % 9;
    int h = sp / 3, w = sp % 3;
    size_t dst = (size_t)bid * K1;
    const float* src = g_roi + (size_t)r * C_ * SPAT;
    for (int idx = threadIdx.x; idx < K1; idx += blockDim.x) {
        int ci = idx / 9, tap = idx % 9;
        int hi = h + tap/3 - 1, wi = w + tap%3 - 1;
        float v = 0.f;
        if (hi >= 0 && hi < 3 && wi >= 0 && wi < 3)
            v = src[ci*9 + hi*3 + wi];
        g_A0[dst + idx] = __float2half(v);
    }
}

// ---------------- 4: pipelined warp-MMA GEMM (fp16, fp32 acc) ------
// CTA tile 64x128, BK=32, 3-stage cp.async, 256 thr = 8 warps (2M x 4N).
// Stage (12KB): A @0 (4KB), B @4096 (8KB). Exact tiling, no bounds checks.
__global__ void __launch_bounds__(256, 2)
gemm_mma(const __half* __restrict__ A0, const __half* __restrict__ B0,
         int kIters, size_t aStride, size_t bStride,
         int rdiv, int rmul,
         float* __restrict__ C, int ldc, size_t cSplit) {
    extern __shared__ char smem[];
    const uint32_t sb = smem_u32(smem);
    const int tid = threadIdx.x;
    const int lane = tid & 31, wid = tid >> 5;
    const int warp_m = wid & 1, warp_n = wid >> 1;
    const int g = lane >> 2, t4 = lane & 3;
    const int row0 = blockIdx.y * 64;
    const int col0 = blockIdx.x * 128;
    const int kStart = blockIdx.z * kIters * 32;

    // load geometry: A 256 chunks (1/thr), B 512 chunks (2/thr)
    const int rA = tid >> 2, ckA = tid & 3;
    const uint32_t dstA = swz(rA, ckA);
    const int grA = row0 + rA;
    const size_t roffA = (size_t)((grA / rdiv) * rmul + (grA % rdiv)) * aStride
                       + (size_t)(ckA * 8);
    const int rB0 = tid >> 2, ckB0 = tid & 3;
    const int rB1 = (tid + 256) >> 2, ckB1 = tid & 3;
    const uint32_t dstB0 = swz(rB0, ckB0);
    const uint32_t dstB1 = swz(rB1, ckB1);
    const size_t goffB0 = (size_t)(col0 + rB0) * bStride + (size_t)(ckB0 * 8);
    const size_t goffB1 = (size_t)(col0 + rB1) * bStride + (size_t)(ckB1 * 8);

    float acc[2][4][4];
    #pragma unroll
    for (int mt = 0; mt < 2; mt++)
        #pragma unroll
        for (int ni = 0; ni < 4; ni++)
            #pragma unroll
            for (int q = 0; q < 4; q++) acc[mt][ni][q] = 0.f;

    // prologue: stages 0,1
    #pragma unroll
    for (int p = 0; p < 2; p++) {
        uint32_t st = sb + p * 12288u;
        int kOff = kStart + p * 32;
        cpasync16(st +    0 + dstA, A0 + roffA + kOff);
        cpasync16(st + 4096 + dstB0, B0 + goffB0 + kOff);
        cpasync16(st + 4096 + dstB1, B0 + goffB1 + kOff);
        CP_COMMIT();
    }

    int sIdx = 0;
    for (int it = 0; it < kIters; it++) {
        if (it + 2 < kIters) {
            int pIdx = sIdx + 2; if (pIdx >= 3) pIdx -= 3;
            uint32_t st = sb + pIdx * 12288u;
            int kOff = kStart + (it + 2) * 32;
            cpasync16(st +    0 + dstA, A0 + roffA + kOff);
            cpasync16(st + 4096 + dstB0, B0 + goffB0 + kOff);
            cpasync16(st + 4096 + dstB1, B0 + goffB1 + kOff);
            CP_COMMIT();
            CP_WAIT2();
        } else if (it + 1 < kIters) {
            CP_WAIT1();
        } else {
            CP_WAIT0();
        }
        __syncthreads();

        const uint32_t st = sb + sIdx * 12288u;
        #pragma unroll
        for (int ksub = 0; ksub < 2; ksub++) {
            const int ckl = ksub*2 + (lane >> 4);
            uint32_t ah[2][4];
            #pragma unroll
            for (int mt = 0; mt < 2; mt++) {
                int row = warp_m*32 + mt*16 + (lane & 15);
                LDSM4(ah[mt], st + swz(row, ckl));
            }
            #pragma unroll
            for (int ni2 = 0; ni2 < 2; ni2++) {
                int row = warp_n*32 + ni2*16 + (lane & 15);
                uint32_t bh[4];
                LDSM4(bh, st + 4096 + swz(row, ckl));
                #pragma unroll
                for (int h = 0; h < 2; h++) {
                    const int ni = ni2*2 + h;
                    #pragma unroll
                    for (int mt = 0; mt < 2; mt++)
                        mma_f16(acc[mt][ni], ah[mt], bh[h], bh[2+h]);
                }
            }
        }
        __syncthreads();
        if (++sIdx == 3) sIdx = 0;
    }

    float* Cb = C + (size_t)blockIdx.z * cSplit;
    #pragma unroll
    for (int mt = 0; mt < 2; mt++) {
        int r_0 = row0 + warp_m*32 + mt*16 + g;
        int r_1 = r_0 + 8;
        #pragma unroll
        for (int ni = 0; ni < 4; ni++) {
            int cc = col0 + warp_n*32 + ni*8 + t4*2;
            *(float2*)(Cb + (size_t)r_0*ldc + cc) =
                make_float2(acc[mt][ni][0], acc[mt][ni][1]);
            *(float2*)(Cb + (size_t)r_1*ldc + cc) =
                make_float2(acc[mt][ni][2], acc[mt][ni][3]);
        }
    }
}

// ---------------- 5: combine P over depth taps + bias + relu -> y (fp16) ---
__global__ void combine_kernel(const float* __restrict__ b1a) {
    int bid = blockIdx.x;           // n*5 + d
    int n = bid / 5, d = bid % 5;
    __shared__ int mm[3];
    if (threadIdx.x < 3) {
        int t = d + threadIdx.x - 1;
        mm[threadIdx.x] = (t >= 0 && t < 5) ? g_map[n*5 + t] : -1;
    }
    __syncthreads();
    for (int idx = threadIdx.x; idx < 9*512; idx += blockDim.x) {
        int sp = idx >> 9, co = idx & 511;
        float acc = b1a[co];
        #pragma unroll
        for (int kd = 0; kd < 3; kd++) {
            int m = mm[kd];
            if (m >= 0)
                acc += g_P[((size_t)(m*9 + sp))*N1 + kd*512 + co];
        }
        g_yh[(size_t)bid*4608 + idx] = __float2half(fmaxf(acc, 0.f));
    }
}

// ---------------- 6: reduce split-K + bias/relu/max/FC ------------
__global__ void maxfc_kernel(const float* __restrict__ b1b,
                             const float* __restrict__ fcw,
                             const float* __restrict__ fcb,
                             float* __restrict__ out) {
    int n = blockIdx.x;
    __shared__ float z[256];
    int c = threadIdx.x;
    float v = -3.4e38f;
    #pragma unroll
    for (int dd = 0; dd < 3; dd++) {
        float s = 0.f;
        #pragma unroll
        for (int zz = 0; zz < SPLIT2; zz++)
            s += g_C2p[(size_t)zz*M2*N2 + (size_t)(n*3 + dd)*N2 + c];
        v = fmaxf(v, s);
    }
    z[c] = fmaxf(v + b1b[c], 0.f);
    __syncthreads();
    int warp = threadIdx.x >> 5, lane = threadIdx.x & 31;
    for (int j = warp; j < NB; j += 8) {
        float s = 0.f;
        #pragma unroll
        for (int q = 0; q < 8; q++)
            s += z[lane + q*32] * fcw[j*256 + lane + q*32];
        #pragma unroll
        for (int off = 16; off; off >>= 1)
            s += __shfl_xor_sync(0xffffffffu, s, off);
        if (lane == 0) out[n*NB + j] = s + fcb[j];
    }
}

// ---------------- launch ----------------
extern "C" void kernel_launch(void* const* d_in, const int* in_sizes, int n_in,
                              void* d_out, int out_size) {
    const float* fmaps = (const float*)d_in[0];
    const float* boxes = (const float*)d_in[1];
    const int*   pids  = (const int*)d_in[2];
    const float* w1a   = (const float*)d_in[3];
    const float* b1a   = (const float*)d_in[4];
    const float* w1b   = (const float*)d_in[5];
    const float* b1b   = (const float*)d_in[6];
    const float* fcw   = (const float*)d_in[7];
    const float* fcb   = (const float*)d_in[8];
    float* out = (float*)d_out;

    __half *pA0, *pB1, *pYh, *pB2;
    float *pP, *pC2p;
    cudaGetSymbolAddress((void**)&pA0, g_A0);
    cudaGetSymbolAddress((void**)&pB1, g_B1);
    cudaGetSymbolAddress((void**)&pYh, g_yh);
    cudaGetSymbolAddress((void**)&pB2, g_B2);
    cudaGetSymbolAddress((void**)&pP,  g_P);
    cudaGetSymbolAddress((void**)&pC2p, g_C2p);

    cudaFuncSetAttribute(gemm_mma, cudaFuncAttributeMaxDynamicSharedMemorySize, 36864);

    prep_map<<<1, 192>>>(pids);
    roi_kernel<<<NBOX, 256>>>(fmaps, boxes);
    w1a_prep<<<(int)(((size_t)N1*K1 + 255)/256), 256>>>(w1a);
    w1b_prep<<<(int)(((size_t)N2*K2 + 255)/256), 256>>>(w1b);
    im2col_f16<<<M1, 256>>>();

    // G1: P[1728x1536] = A[1728x9216] * B[1536x9216]^T  (324 CTAs)
    gemm_mma<<<dim3(N1/128, M1/64, 1), 256, 36864>>>(
        pA0, pB1, K1/32, K1, K1, 1, 1, pP, N1, 0);

    combine_kernel<<<NBOX*5, 256>>>(b1a);

    // G2 split-K=8: C2p[z][576x256] = y * B2^T, row remap (r/3)*5 + r%3
    gemm_mma<<<dim3(N2/128, M2/64, SPLIT2), 256, 36864>>>(
        pYh, pB2, KIT2, 4608, K2, 3, 5, pC2p, N2, (size_t)M2*N2);

    maxfc_kernel<<<NBOX, 256>>>(b1b, fcw, fcb, out);
}

// round 9
// speedup vs baseline: 5.3018x; 1.1078x over previous
#include <cuda_runtime.h>
#include <cuda_fp16.h>
#include <cstdint>

// ---------------- problem constants ----------------
#define F_    32
#define B_    6
#define C_    1024
#define HF    14
#define NB    27
#define T_    5
#define OUTP  3
#define SPAT  9
#define NBOX  (F_*B_)           // 192
#define K1    (C_*SPAT)         // 9216
#define N1    (3*512)           // 1536
#define M1    (NBOX*SPAT)       // 1728 = 27*64
#define K2    (512*27)          // 13824
#define M2    (NBOX*3)          // 576 = 9*64
#define N2    256
#define SPLIT1 2
#define KIT1  144               // 9216/2/32
#define SPLIT2 8
#define KIT2  54                // 13824/8/32

// ---------------- scratch ----------------
__device__ int   g_map[NBOX*T_];
__device__ __align__(16) __half g_A0[(size_t)M1*K1];   // im2col fp16
__device__ __align__(16) __half g_B1[(size_t)N1*K1];   // w1a [n][k] fp16
__device__ float g_P [(size_t)SPLIT1*M1*N1];           // G1 split-K partials
__device__ __align__(16) __half g_yh[(size_t)NBOX*5*4608];
__device__ __align__(16) __half g_B2[(size_t)N2*K2];   // w1b [n][k] fp16
__device__ float g_C2p[(size_t)SPLIT2*M2*N2];

// ---------------- helpers ----------------
__device__ __forceinline__ void cpasync16(uint32_t dst, const void* src) {
    asm volatile("cp.async.cg.shared.global [%0], [%1], 16;"
                 :: "r"(dst), "l"(__cvta_generic_to_global(src)) : "memory");
}
__device__ __forceinline__ uint32_t smem_u32(const void* p) {
    uint32_t a;
    asm("{ .reg .u64 t; cvta.to.shared.u64 t, %1; cvt.u32.u64 %0, t; }"
        : "=r"(a) : "l"(p));
    return a;
}
#define CP_COMMIT() asm volatile("cp.async.commit_group;" ::: "memory")
#define CP_WAIT2()  asm volatile("cp.async.wait_group 2;" ::: "memory")
#define CP_WAIT1()  asm volatile("cp.async.wait_group 1;" ::: "memory")
#define CP_WAIT0()  asm volatile("cp.async.wait_group 0;" ::: "memory")
#define LDSM4(rr, a) asm volatile( \
    "ldmatrix.sync.aligned.m8n8.x4.shared.b16 {%0,%1,%2,%3}, [%4];" \
    : "=r"((rr)[0]),"=r"((rr)[1]),"=r"((rr)[2]),"=r"((rr)[3]) : "r"(a))
__device__ __forceinline__ void mma_f16(float* d, const uint32_t* a,
                                        uint32_t b0, uint32_t b1) {
    asm volatile(
        "mma.sync.aligned.m16n8k16.row.col.f32.f16.f16.f32 "
        "{%0,%1,%2,%3}, {%4,%5,%6,%7}, {%8,%9}, {%0,%1,%2,%3};"
        : "+f"(d[0]), "+f"(d[1]), "+f"(d[2]), "+f"(d[3])
        : "r"(a[0]), "r"(a[1]), "r"(a[2]), "r"(a[3]), "r"(b0), "r"(b1));
}
// swizzled byte offset within rows x 32 fp16 tile (64B rows, 16B chunks)
__device__ __forceinline__ uint32_t swz(int row, int ckl) {
    return (uint32_t)row*64u + (uint32_t)((ckl ^ (row & 3)) << 4);
}

// ---------------- 0: temporal index + person matching ----------------
__global__ void prep_map(const int* __restrict__ person_ids) {
    int n = threadIdx.x;
    if (n >= NBOX) return;
    int f = n / B_, b = n % B_;
    int pid = person_ids[f*B_ + b];
    int start = max(f - T_/2, 0);
    int end   = min(start + T_ - 1, F_ - 1);
    for (int t = 0; t < T_; t++) {
        int g = (int)((float)start + (float)(t*(end-start)) / (float)(T_-1));
        int m = -1;
        for (int bp = 0; bp < B_; bp++)
            if (person_ids[g*B_ + bp] == pid) m = g*B_ + bp;
        g_map[n*T_ + t] = m;
    }
}

// ---------------- 1: fused ROI align + im2col -> g_A0 (fp16) ----------------
__global__ void roi_im2col(const float* __restrict__ fmaps,
                           const float* __restrict__ boxes) {
    __shared__ __half sroi[C_*SPAT];     // 18KB
    __shared__ int   sy0[6], sy1[6], sx0[6], sx1[6];
    __shared__ float sly[6], slx[6];
    int nb = blockIdx.x;
    int f  = nb / B_;
    if (threadIdx.x < 12) {
        int  j   = threadIdx.x % 6;
        bool isx = threadIdx.x >= 6;
        float x1 = boxes[nb*4+0], y1 = boxes[nb*4+1];
        float x2 = boxes[nb*4+2], y2 = boxes[nb*4+3];
        float bw = fmaxf(x2 - x1, 1.0f) / (float)OUTP;
        float bh = fmaxf(y2 - y1, 1.0f) / (float)OUTP;
        float gj = (float)(j >> 1) + ((float)(j & 1) + 0.5f) * 0.5f;
        if (isx) {
            float xs  = x1 + bw * gj;
            float x0f = fminf(fmaxf(floorf(xs), 0.f), (float)(HF-1));
            float lx  = fminf(fmaxf(xs - x0f, 0.f), 1.f);
            int x0 = (int)x0f;
            sx0[j] = x0; sx1[j] = min(x0+1, HF-1); slx[j] = lx;
        } else {
            float ys  = y1 + bh * gj;
            float y0f = fminf(fmaxf(floorf(ys), 0.f), (float)(HF-1));
            float ly  = fminf(fmaxf(ys - y0f, 0.f), 1.f);
            int y0 = (int)y0f;
            sy0[j] = y0; sy1[j] = min(y0+1, HF-1); sly[j] = ly;
        }
    }
    __syncthreads();
    const float* base = fmaps + (size_t)f * C_ * HF * HF;
    for (int idx = threadIdx.x; idx < C_*SPAT; idx += blockDim.x) {
        int c = idx / SPAT, o = idx % SPAT;
        int oi = o / 3, oj = o % 3;
        const float* fm = base + (size_t)c * HF * HF;
        float acc = 0.f;
        #pragma unroll
        for (int s = 0; s < 4; s++) {
            int jy = oi*2 + (s >> 1);
            int jx = oj*2 + (s & 1);
            float ly = sly[jy], lx = slx[jx];
            int y0 = sy0[jy], y1i = sy1[jy], x0 = sx0[jx], x1i = sx1[jx];
            acc += fm[y0*HF + x0]  * (1.f-ly)*(1.f-lx)
                 + fm[y0*HF + x1i] * (1.f-ly)*lx
                 + fm[y1i*HF + x0] * ly*(1.f-lx)
                 + fm[y1i*HF + x1i]* ly*lx;
        }
        sroi[idx] = __float2half(acc * 0.25f);
    }
    __syncthreads();
    const __half hz = __float2half(0.f);
    #pragma unroll
    for (int sp = 0; sp < SPAT; sp++) {
        int h = sp / 3, w = sp % 3;
        __half* dst = g_A0 + ((size_t)(nb*9 + sp)) * K1;
        for (int idx = threadIdx.x; idx < K1; idx += blockDim.x) {
            int ci = idx / 9, tap = idx % 9;
            int hi = h + tap/3 - 1, wi = w + tap%3 - 1;
            dst[idx] = (hi >= 0 && hi < 3 && wi >= 0 && wi < 3)
                       ? sroi[ci*9 + hi*3 + wi] : hz;
        }
    }
}

// ---------------- 2a: w1a -> fp16 via smem transpose (block per co) --------
// in:  w[co][ci*27 + kd*9 + tap]   (coalesced read)
// out: g_B1[(kd*512+co)*9216 + ci*9+tap]  (coalesced write)
__global__ void w1a_prep(const float* __restrict__ w) {
    extern __shared__ __half sh[];       // 27648 halves = 55296B
    int co = blockIdx.x;
    const float* src = w + (size_t)co * 27648;
    for (int i = threadIdx.x; i < 27648; i += 256) {
        int ci = i / 27, q = i % 27;
        int kd = q / 9, tap = q % 9;
        sh[kd*9216 + ci*9 + tap] = __float2half(src[i]);
    }
    __syncthreads();
    const uint4* shv = (const uint4*)sh;
    #pragma unroll
    for (int kd = 0; kd < 3; kd++) {
        uint4* dst = (uint4*)(g_B1 + ((size_t)(kd*512 + co)) * 9216);
        for (int j = threadIdx.x; j < 1152; j += 256)
            dst[j] = shv[kd*1152 + j];
    }
}
// ---------------- 2b: w1b -> fp16 via smem transpose (block per n) ---------
// in:  w[n][ci*27 + q]; out: g_B2[n*13824 + q*512 + ci]
__global__ void w1b_prep(const float* __restrict__ w) {
    extern __shared__ __half sh2[];      // 13824 halves = 27648B
    int n = blockIdx.x;
    const float* src = w + (size_t)n * 13824;
    for (int i = threadIdx.x; i < 13824; i += 256) {
        int ci = i / 27, q = i % 27;
        sh2[q*512 + ci] = __float2half(src[i]);
    }
    __syncthreads();
    const uint4* shv = (const uint4*)sh2;
    uint4* dst = (uint4*)(g_B2 + (size_t)n * 13824);
    for (int j = threadIdx.x; j < 1728; j += 256)
        dst[j] = shv[j];
}

// ---------------- 4: pipelined warp-MMA GEMM (fp16, fp32 acc) ------
// CTA tile 64x128, BK=32, 3-stage cp.async, 256 thr = 8 warps (2M x 4N).
// Stage (12KB): A @0 (4KB), B @4096 (8KB). Exact tiling, no bounds checks.
__global__ void __launch_bounds__(256, 2)
gemm_mma(const __half* __restrict__ A0, const __half* __restrict__ B0,
         int kIters, size_t aStride, size_t bStride,
         int rdiv, int rmul,
         float* __restrict__ C, int ldc, size_t cSplit) {
    extern __shared__ char smem[];
    const uint32_t sb = smem_u32(smem);
    const int tid = threadIdx.x;
    const int lane = tid & 31, wid = tid >> 5;
    const int warp_m = wid & 1, warp_n = wid >> 1;
    const int g = lane >> 2, t4 = lane & 3;
    const int row0 = blockIdx.y * 64;
    const int col0 = blockIdx.x * 128;
    const int kStart = blockIdx.z * kIters * 32;

    const int rA = tid >> 2, ckA = tid & 3;
    const uint32_t dstA = swz(rA, ckA);
    const int grA = row0 + rA;
    const size_t roffA = (size_t)((grA / rdiv) * rmul + (grA % rdiv)) * aStride
                       + (size_t)(ckA * 8);
    const int rB0 = tid >> 2, ckB0 = tid & 3;
    const int rB1 = (tid + 256) >> 2, ckB1 = tid & 3;
    const uint32_t dstB0 = swz(rB0, ckB0);
    const uint32_t dstB1 = swz(rB1, ckB1);
    const size_t goffB0 = (size_t)(col0 + rB0) * bStride + (size_t)(ckB0 * 8);
    const size_t goffB1 = (size_t)(col0 + rB1) * bStride + (size_t)(ckB1 * 8);

    float acc[2][4][4];
    #pragma unroll
    for (int mt = 0; mt < 2; mt++)
        #pragma unroll
        for (int ni = 0; ni < 4; ni++)
            #pragma unroll
            for (int q = 0; q < 4; q++) acc[mt][ni][q] = 0.f;

    #pragma unroll
    for (int p = 0; p < 2; p++) {
        uint32_t st = sb + p * 12288u;
        int kOff = kStart + p * 32;
        cpasync16(st +    0 + dstA, A0 + roffA + kOff);
        cpasync16(st + 4096 + dstB0, B0 + goffB0 + kOff);
        cpasync16(st + 4096 + dstB1, B0 + goffB1 + kOff);
        CP_COMMIT();
    }

    int sIdx = 0;
    for (int it = 0; it < kIters; it++) {
        if (it + 2 < kIters) {
            int pIdx = sIdx + 2; if (pIdx >= 3) pIdx -= 3;
            uint32_t st = sb + pIdx * 12288u;
            int kOff = kStart + (it + 2) * 32;
            cpasync16(st +    0 + dstA, A0 + roffA + kOff);
            cpasync16(st + 4096 + dstB0, B0 + goffB0 + kOff);
            cpasync16(st + 4096 + dstB1, B0 + goffB1 + kOff);
            CP_COMMIT();
            CP_WAIT2();
        } else if (it + 1 < kIters) {
            CP_WAIT1();
        } else {
            CP_WAIT0();
        }
        __syncthreads();

        const uint32_t st = sb + sIdx * 12288u;
        #pragma unroll
        for (int ksub = 0; ksub < 2; ksub++) {
            const int ckl = ksub*2 + (lane >> 4);
            uint32_t ah[2][4];
            #pragma unroll
            for (int mt = 0; mt < 2; mt++) {
                int row = warp_m*32 + mt*16 + (lane & 15);
                LDSM4(ah[mt], st + swz(row, ckl));
            }
            #pragma unroll
            for (int ni2 = 0; ni2 < 2; ni2++) {
                int row = warp_n*32 + ni2*16 + (lane & 15);
                uint32_t bh[4];
                LDSM4(bh, st + 4096 + swz(row, ckl));
                #pragma unroll
                for (int h = 0; h < 2; h++) {
                    const int ni = ni2*2 + h;
                    #pragma unroll
                    for (int mt = 0; mt < 2; mt++)
                        mma_f16(acc[mt][ni], ah[mt], bh[h], bh[2+h]);
                }
            }
        }
        __syncthreads();
        if (++sIdx == 3) sIdx = 0;
    }

    float* Cb = C + (size_t)blockIdx.z * cSplit;
    #pragma unroll
    for (int mt = 0; mt < 2; mt++) {
        int r_0 = row0 + warp_m*32 + mt*16 + g;
        int r_1 = r_0 + 8;
        #pragma unroll
        for (int ni = 0; ni < 4; ni++) {
            int cc = col0 + warp_n*32 + ni*8 + t4*2;
            *(float2*)(Cb + (size_t)r_0*ldc + cc) =
                make_float2(acc[mt][ni][0], acc[mt][ni][1]);
            *(float2*)(Cb + (size_t)r_1*ldc + cc) =
                make_float2(acc[mt][ni][2], acc[mt][ni][3]);
        }
    }
}

// ---------------- 5: combine split-K P + depth taps + bias + relu -> y -----
__global__ void combine_kernel(const float* __restrict__ b1a) {
    int bid = blockIdx.x;           // n*5 + d
    int n = bid / 5, d = bid % 5;
    __shared__ int mm[3];
    if (threadIdx.x < 3) {
        int t = d + threadIdx.x - 1;
        mm[threadIdx.x] = (t >= 0 && t < 5) ? g_map[n*5 + t] : -1;
    }
    __syncthreads();
    const size_t PS = (size_t)M1 * N1;
    for (int idx = threadIdx.x; idx < 9*512; idx += blockDim.x) {
        int sp = idx >> 9, co = idx & 511;
        float acc = b1a[co];
        #pragma unroll
        for (int kd = 0; kd < 3; kd++) {
            int m = mm[kd];
            if (m >= 0) {
                size_t o = ((size_t)(m*9 + sp))*N1 + kd*512 + co;
                acc += g_P[o] + g_P[PS + o];
            }
        }
        g_yh[(size_t)bid*4608 + idx] = __float2half(fmaxf(acc, 0.f));
    }
}

// ---------------- 6: reduce split-K + bias/relu/max/FC ------------
__global__ void maxfc_kernel(const float* __restrict__ b1b,
                             const float* __restrict__ fcw,
                             const float* __restrict__ fcb,
                             float* __restrict__ out) {
    int n = blockIdx.x;
    __shared__ float z[256];
    int c = threadIdx.x;
    float v = -3.4e38f;
    #pragma unroll
    for (int dd = 0; dd < 3; dd++) {
        float s = 0.f;
        #pragma unroll
        for (int zz = 0; zz < SPLIT2; zz++)
            s += g_C2p[(size_t)zz*M2*N2 + (size_t)(n*3 + dd)*N2 + c];
        v = fmaxf(v, s);
    }
    z[c] = fmaxf(v + b1b[c], 0.f);
    __syncthreads();
    int warp = threadIdx.x >> 5, lane = threadIdx.x & 31;
    for (int j = warp; j < NB; j += 8) {
        float s = 0.f;
        #pragma unroll
        for (int q = 0; q < 8; q++)
            s += z[lane + q*32] * fcw[j*256 + lane + q*32];
        #pragma unroll
        for (int off = 16; off; off >>= 1)
            s += __shfl_xor_sync(0xffffffffu, s, off);
        if (lane == 0) out[n*NB + j] = s + fcb[j];
    }
}

// ---------------- launch ----------------
extern "C" void kernel_launch(void* const* d_in, const int* in_sizes, int n_in,
                              void* d_out, int out_size) {
    const float* fmaps = (const float*)d_in[0];
    const float* boxes = (const float*)d_in[1];
    const int*   pids  = (const int*)d_in[2];
    const float* w1a   = (const float*)d_in[3];
    const float* b1a   = (const float*)d_in[4];
    const float* w1b   = (const float*)d_in[5];
    const float* b1b   = (const float*)d_in[6];
    const float* fcw   = (const float*)d_in[7];
    const float* fcb   = (const float*)d_in[8];
    float* out = (float*)d_out;

    __half *pA0, *pB1, *pYh, *pB2;
    float *pP, *pC2p;
    cudaGetSymbolAddress((void**)&pA0, g_A0);
    cudaGetSymbolAddress((void**)&pB1, g_B1);
    cudaGetSymbolAddress((void**)&pYh, g_yh);
    cudaGetSymbolAddress((void**)&pB2, g_B2);
    cudaGetSymbolAddress((void**)&pP,  g_P);
    cudaGetSymbolAddress((void**)&pC2p, g_C2p);

    cudaFuncSetAttribute(gemm_mma, cudaFuncAttributeMaxDynamicSharedMemorySize, 36864);
    cudaFuncSetAttribute(w1a_prep, cudaFuncAttributeMaxDynamicSharedMemorySize, 55296);

    prep_map<<<1, 192>>>(pids);
    roi_im2col<<<NBOX, 256>>>(fmaps, boxes);
    w1a_prep<<<512, 256, 55296>>>(w1a);
    w1b_prep<<<256, 256, 27648>>>(w1b);

    // G1 split-K=2: P[z][1728x1536] = A[1728x9216] * B[1536x9216]^T
    gemm_mma<<<dim3(N1/128, M1/64, SPLIT1), 256, 36864>>>(
        pA0, pB1, KIT1, K1, K1, 1, 1, pP, N1, (size_t)M1*N1);

    combine_kernel<<<NBOX*5, 256>>>(b1a);

    // G2 split-K=8: C2p[z][576x256] = y * B2^T, row remap (r/3)*5 + r%3
    gemm_mma<<<dim3(N2/128, M2/64, SPLIT2), 256, 36864>>>(
        pYh, pB2, KIT2, 4608, K2, 3, 5, pC2p, N2, (size_t)M2*N2);

    maxfc_kernel<<<NBOX, 256>>>(b1b, fcw, fcb, out);
}

// round 10
// speedup vs baseline: 6.2559x; 1.1800x over previous
#include <cuda_runtime.h>
#include <cuda_fp16.h>
#include <cstdint>

// ---------------- problem constants ----------------
#define F_    32
#define B_    6
#define C_    1024
#define HF    14
#define NB    27
#define T_    5
#define OUTP  3
#define SPAT  9
#define NBOX  (F_*B_)           // 192
#define K1    (C_*SPAT)         // 9216
#define N1    (3*512)           // 1536
#define M1    (NBOX*SPAT)       // 1728 = 27*64
#define K2    (512*27)          // 13824
#define M2    (NBOX*3)          // 576 = 9*64
#define N2    256
#define SPLIT1 2
#define KIT1  144               // 9216/2/32
#define SPLIT2 8
#define KIT2  54                // 13824/8/32

// ---------------- scratch ----------------
__device__ int   g_map[NBOX*T_];
__device__ __align__(16) __half g_A0[(size_t)M1*K1];   // im2col fp16
__device__ __align__(16) __half g_B1[(size_t)N1*K1];   // w1a [n][k] fp16
__device__ float g_P [(size_t)SPLIT1*M1*N1];           // G1 split-K partials
__device__ __align__(16) __half g_yh[(size_t)NBOX*5*4608];
__device__ __align__(16) __half g_B2[(size_t)N2*K2];   // w1b [n][k] fp16
__device__ float g_C2p[(size_t)SPLIT2*M2*N2];

// ---------------- helpers ----------------
__device__ __forceinline__ void cpasync16(uint32_t dst, const void* src) {
    asm volatile("cp.async.cg.shared.global [%0], [%1], 16;"
                 :: "r"(dst), "l"(__cvta_generic_to_global(src)) : "memory");
}
__device__ __forceinline__ uint32_t smem_u32(const void* p) {
    uint32_t a;
    asm("{ .reg .u64 t; cvta.to.shared.u64 t, %1; cvt.u32.u64 %0, t; }"
        : "=r"(a) : "l"(p));
    return a;
}
#define CP_COMMIT() asm volatile("cp.async.commit_group;" ::: "memory")
#define CP_WAIT2()  asm volatile("cp.async.wait_group 2;" ::: "memory")
#define CP_WAIT1()  asm volatile("cp.async.wait_group 1;" ::: "memory")
#define CP_WAIT0()  asm volatile("cp.async.wait_group 0;" ::: "memory")
#define LDSM4(rr, a) asm volatile( \
    "ldmatrix.sync.aligned.m8n8.x4.shared.b16 {%0,%1,%2,%3}, [%4];" \
    : "=r"((rr)[0]),"=r"((rr)[1]),"=r"((rr)[2]),"=r"((rr)[3]) : "r"(a))
__device__ __forceinline__ void mma_f16(float* d, const uint32_t* a,
                                        uint32_t b0, uint32_t b1) {
    asm volatile(
        "mma.sync.aligned.m16n8k16.row.col.f32.f16.f16.f32 "
        "{%0,%1,%2,%3}, {%4,%5,%6,%7}, {%8,%9}, {%0,%1,%2,%3};"
        : "+f"(d[0]), "+f"(d[1]), "+f"(d[2]), "+f"(d[3])
        : "r"(a[0]), "r"(a[1]), "r"(a[2]), "r"(a[3]), "r"(b0), "r"(b1));
}
// swizzled byte offset within rows x 32 fp16 tile (64B rows, 16B chunks)
__device__ __forceinline__ uint32_t swz(int row, int ckl) {
    return (uint32_t)row*64u + (uint32_t)((ckl ^ (row & 3)) << 4);
}
__device__ __forceinline__ uint32_t pack2(__half a, __half b) {
    __half2 h2 = __halves2half2(a, b);
    return *(uint32_t*)&h2;
}

// ---------------- fused prep: roi+im2col | w1a | w1b | map ----------------
// grid 961 x 256 thr, 55296B dynamic smem.
//  blocks [0,192):   ROI align + im2col -> g_A0
//  blocks [192,704): w1a transpose (co = b-192) -> g_B1
//  blocks [704,960): w1b transpose (n = b-704)  -> g_B2
//  block  960:       temporal person map -> g_map
__global__ void __launch_bounds__(256)
prep_all(const float* __restrict__ fmaps, const float* __restrict__ boxes,
         const int* __restrict__ person_ids,
         const float* __restrict__ w1a, const float* __restrict__ w1b) {
    extern __shared__ char dyn[];
    const int bb = blockIdx.x;
    const int tid = threadIdx.x;

    if (bb < 192) {
        // ---------- ROI align + im2col ----------
        __half* sroi = (__half*)dyn;             // 9216 halves = 18KB
        __shared__ int   sy0[6], sy1[6], sx0[6], sx1[6];
        __shared__ float sly[6], slx[6];
        int nb = bb;
        int f  = nb / B_;
        if (tid < 12) {
            int  j   = tid % 6;
            bool isx = tid >= 6;
            float x1 = boxes[nb*4+0], y1 = boxes[nb*4+1];
            float x2 = boxes[nb*4+2], y2 = boxes[nb*4+3];
            float bw = fmaxf(x2 - x1, 1.0f) / (float)OUTP;
            float bh = fmaxf(y2 - y1, 1.0f) / (float)OUTP;
            float gj = (float)(j >> 1) + ((float)(j & 1) + 0.5f) * 0.5f;
            if (isx) {
                float xs  = x1 + bw * gj;
                float x0f = fminf(fmaxf(floorf(xs), 0.f), (float)(HF-1));
                float lx  = fminf(fmaxf(xs - x0f, 0.f), 1.f);
                int x0 = (int)x0f;
                sx0[j] = x0; sx1[j] = min(x0+1, HF-1); slx[j] = lx;
            } else {
                float ys  = y1 + bh * gj;
                float y0f = fminf(fmaxf(floorf(ys), 0.f), (float)(HF-1));
                float ly  = fminf(fmaxf(ys - y0f, 0.f), 1.f);
                int y0 = (int)y0f;
                sy0[j] = y0; sy1[j] = min(y0+1, HF-1); sly[j] = ly;
            }
        }
        __syncthreads();
        const float* base = fmaps + (size_t)f * C_ * HF * HF;
        for (int idx = tid; idx < C_*SPAT; idx += 256) {
            int c = idx / SPAT, o = idx % SPAT;
            int oi = o / 3, oj = o % 3;
            const float* fm = base + (size_t)c * HF * HF;
            float acc = 0.f;
            #pragma unroll
            for (int s = 0; s < 4; s++) {
                int jy = oi*2 + (s >> 1);
                int jx = oj*2 + (s & 1);
                float ly = sly[jy], lx = slx[jx];
                int y0 = sy0[jy], y1i = sy1[jy], x0 = sx0[jx], x1i = sx1[jx];
                acc += fm[y0*HF + x0]  * (1.f-ly)*(1.f-lx)
                     + fm[y0*HF + x1i] * (1.f-ly)*lx
                     + fm[y1i*HF + x0] * ly*(1.f-lx)
                     + fm[y1i*HF + x1i]* ly*lx;
            }
            sroi[idx] = __float2half(acc * 0.25f);
        }
        __syncthreads();
        const __half hz = __float2half(0.f);
        #pragma unroll
        for (int sp = 0; sp < SPAT; sp++) {
            int h = sp / 3, w = sp % 3;
            uint32_t* dst = (uint32_t*)(g_A0 + ((size_t)(nb*9 + sp)) * K1);
            for (int jj = tid; jj < K1/2; jj += 256) {
                int j0 = 2*jj, j1 = 2*jj + 1;
                int ci0 = j0 / 9, t0 = j0 % 9;
                int ci1 = j1 / 9, t1 = j1 % 9;
                int h0 = h + t0/3 - 1, w0 = w + t0%3 - 1;
                int h1 = h + t1/3 - 1, w1 = w + t1%3 - 1;
                __half v0 = (h0 >= 0 && h0 < 3 && w0 >= 0 && w0 < 3)
                            ? sroi[ci0*9 + h0*3 + w0] : hz;
                __half v1 = (h1 >= 0 && h1 < 3 && w1 >= 0 && w1 < 3)
                            ? sroi[ci1*9 + h1*3 + w1] : hz;
                dst[jj] = pack2(v0, v1);
            }
        }
    } else if (bb < 704) {
        // ---------- w1a: linear smem fp16, gather on read ----------
        __half* sh = (__half*)dyn;               // 27648 halves = 55296B
        int co = bb - 192;
        const float* src = w1a + (size_t)co * 27648;
        for (int i = tid; i < 27648; i += 256)
            sh[i] = __float2half(src[i]);        // conflict-free STS
        __syncthreads();
        #pragma unroll
        for (int kd = 0; kd < 3; kd++) {
            uint32_t* dst = (uint32_t*)(g_B1 + ((size_t)(kd*512 + co)) * 9216);
            const int kb = kd * 9;
            for (int jj = tid; jj < 4608; jj += 256) {
                int j0 = 2*jj, j1 = j0 + 1;
                int ci0 = j0 / 9, t0 = j0 % 9;
                int ci1 = j1 / 9, t1 = j1 % 9;
                dst[jj] = pack2(sh[ci0*27 + kb + t0], sh[ci1*27 + kb + t1]);
            }
        }
    } else if (bb < 960) {
        // ---------- w1b: linear smem fp16, gather on read ----------
        __half* sh = (__half*)dyn;               // 13824 halves = 27648B
        int n = bb - 704;
        const float* src = w1b + (size_t)n * 13824;
        for (int i = tid; i < 13824; i += 256)
            sh[i] = __float2half(src[i]);
        __syncthreads();
        uint32_t* dst = (uint32_t*)(g_B2 + (size_t)n * 13824);
        for (int jj = tid; jj < 6912; jj += 256) {
            int j = 2*jj;
            int q = j >> 9, ci = j & 511;        // pairs never cross q
            dst[jj] = pack2(sh[ci*27 + q], sh[(ci+1)*27 + q]);
        }
    } else {
        // ---------- temporal index + person matching ----------
        int n = tid;
        if (n < NBOX) {
            int f = n / B_, b = n % B_;
            int pid = person_ids[f*B_ + b];
            int start = max(f - T_/2, 0);
            int end   = min(start + T_ - 1, F_ - 1);
            for (int t = 0; t < T_; t++) {
                int g = (int)((float)start + (float)(t*(end-start)) / (float)(T_-1));
                int m = -1;
                for (int bp = 0; bp < B_; bp++)
                    if (person_ids[g*B_ + bp] == pid) m = g*B_ + bp;
                g_map[n*T_ + t] = m;
            }
        }
    }
}

// ---------------- pipelined warp-MMA GEMM (fp16, fp32 acc) ------
// CTA tile 64x128, BK=32, 3-stage cp.async, 256 thr = 8 warps (2M x 4N).
// Stage (12KB): A @0 (4KB), B @4096 (8KB). Exact tiling, no bounds checks.
__global__ void __launch_bounds__(256, 2)
gemm_mma(const __half* __restrict__ A0, const __half* __restrict__ B0,
         int kIters, size_t aStride, size_t bStride,
         int rdiv, int rmul,
         float* __restrict__ C, int ldc, size_t cSplit) {
    extern __shared__ char smem[];
    const uint32_t sb = smem_u32(smem);
    const int tid = threadIdx.x;
    const int lane = tid & 31, wid = tid >> 5;
    const int warp_m = wid & 1, warp_n = wid >> 1;
    const int g = lane >> 2, t4 = lane & 3;
    const int row0 = blockIdx.y * 64;
    const int col0 = blockIdx.x * 128;
    const int kStart = blockIdx.z * kIters * 32;

    const int rA = tid >> 2, ckA = tid & 3;
    const uint32_t dstA = swz(rA, ckA);
    const int grA = row0 + rA;
    const size_t roffA = (size_t)((grA / rdiv) * rmul + (grA % rdiv)) * aStride
                       + (size_t)(ckA * 8);
    const int rB0 = tid >> 2, ckB0 = tid & 3;
    const int rB1 = (tid + 256) >> 2, ckB1 = tid & 3;
    const uint32_t dstB0 = swz(rB0, ckB0);
    const uint32_t dstB1 = swz(rB1, ckB1);
    const size_t goffB0 = (size_t)(col0 + rB0) * bStride + (size_t)(ckB0 * 8);
    const size_t goffB1 = (size_t)(col0 + rB1) * bStride + (size_t)(ckB1 * 8);

    float acc[2][4][4];
    #pragma unroll
    for (int mt = 0; mt < 2; mt++)
        #pragma unroll
        for (int ni = 0; ni < 4; ni++)
            #pragma unroll
            for (int q = 0; q < 4; q++) acc[mt][ni][q] = 0.f;

    #pragma unroll
    for (int p = 0; p < 2; p++) {
        uint32_t st = sb + p * 12288u;
        int kOff = kStart + p * 32;
        cpasync16(st +    0 + dstA, A0 + roffA + kOff);
        cpasync16(st + 4096 + dstB0, B0 + goffB0 + kOff);
        cpasync16(st + 4096 + dstB1, B0 + goffB1 + kOff);
        CP_COMMIT();
    }

    int sIdx = 0;
    for (int it = 0; it < kIters; it++) {
        if (it + 2 < kIters) {
            int pIdx = sIdx + 2; if (pIdx >= 3) pIdx -= 3;
            uint32_t st = sb + pIdx * 12288u;
            int kOff = kStart + (it + 2) * 32;
            cpasync16(st +    0 + dstA, A0 + roffA + kOff);
            cpasync16(st + 4096 + dstB0, B0 + goffB0 + kOff);
            cpasync16(st + 4096 + dstB1, B0 + goffB1 + kOff);
            CP_COMMIT();
            CP_WAIT2();
        } else if (it + 1 < kIters) {
            CP_WAIT1();
        } else {
            CP_WAIT0();
        }
        __syncthreads();

        const uint32_t st = sb + sIdx * 12288u;
        #pragma unroll
        for (int ksub = 0; ksub < 2; ksub++) {
            const int ckl = ksub*2 + (lane >> 4);
            uint32_t ah[2][4];
            #pragma unroll
            for (int mt = 0; mt < 2; mt++) {
                int row = warp_m*32 + mt*16 + (lane & 15);
                LDSM4(ah[mt], st + swz(row, ckl));
            }
            #pragma unroll
            for (int ni2 = 0; ni2 < 2; ni2++) {
                int row = warp_n*32 + ni2*16 + (lane & 15);
                uint32_t bh[4];
                LDSM4(bh, st + 4096 + swz(row, ckl));
                #pragma unroll
                for (int h = 0; h < 2; h++) {
                    const int ni = ni2*2 + h;
                    #pragma unroll
                    for (int mt = 0; mt < 2; mt++)
                        mma_f16(acc[mt][ni], ah[mt], bh[h], bh[2+h]);
                }
            }
        }
        __syncthreads();
        if (++sIdx == 3) sIdx = 0;
    }

    float* Cb = C + (size_t)blockIdx.z * cSplit;
    #pragma unroll
    for (int mt = 0; mt < 2; mt++) {
        int r_0 = row0 + warp_m*32 + mt*16 + g;
        int r_1 = r_0 + 8;
        #pragma unroll
        for (int ni = 0; ni < 4; ni++) {
            int cc = col0 + warp_n*32 + ni*8 + t4*2;
            *(float2*)(Cb + (size_t)r_0*ldc + cc) =
                make_float2(acc[mt][ni][0], acc[mt][ni][1]);
            *(float2*)(Cb + (size_t)r_1*ldc + cc) =
                make_float2(acc[mt][ni][2], acc[mt][ni][3]);
        }
    }
}

// ---------------- combine split-K P + depth taps + bias + relu -> y -----
__global__ void combine_kernel(const float* __restrict__ b1a) {
    int bid = blockIdx.x;           // n*5 + d
    int n = bid / 5, d = bid % 5;
    __shared__ int mm[3];
    if (threadIdx.x < 3) {
        int t = d + threadIdx.x - 1;
        mm[threadIdx.x] = (t >= 0 && t < 5) ? g_map[n*5 + t] : -1;
    }
    __syncthreads();
    const size_t PS = (size_t)M1 * N1;
    for (int idx = threadIdx.x; idx < 9*512; idx += blockDim.x) {
        int sp = idx >> 9, co = idx & 511;
        float acc = b1a[co];
        #pragma unroll
        for (int kd = 0; kd < 3; kd++) {
            int m = mm[kd];
            if (m >= 0) {
                size_t o = ((size_t)(m*9 + sp))*N1 + kd*512 + co;
                acc += g_P[o] + g_P[PS + o];
            }
        }
        g_yh[(size_t)bid*4608 + idx] = __float2half(fmaxf(acc, 0.f));
    }
}

// ---------------- reduce split-K + bias/relu/max/FC ------------
__global__ void maxfc_kernel(const float* __restrict__ b1b,
                             const float* __restrict__ fcw,
                             const float* __restrict__ fcb,
                             float* __restrict__ out) {
    int n = blockIdx.x;
    __shared__ float z[256];
    int c = threadIdx.x;
    float v = -3.4e38f;
    #pragma unroll
    for (int dd = 0; dd < 3; dd++) {
        float s = 0.f;
        #pragma unroll
        for (int zz = 0; zz < SPLIT2; zz++)
            s += g_C2p[(size_t)zz*M2*N2 + (size_t)(n*3 + dd)*N2 + c];
        v = fmaxf(v, s);
    }
    z[c] = fmaxf(v + b1b[c], 0.f);
    __syncthreads();
    int warp = threadIdx.x >> 5, lane = threadIdx.x & 31;
    for (int j = warp; j < NB; j += 8) {
        float s = 0.f;
        #pragma unroll
        for (int q = 0; q < 8; q++)
            s += z[lane + q*32] * fcw[j*256 + lane + q*32];
        #pragma unroll
        for (int off = 16; off; off >>= 1)
            s += __shfl_xor_sync(0xffffffffu, s, off);
        if (lane == 0) out[n*NB + j] = s + fcb[j];
    }
}

// ---------------- launch ----------------
extern "C" void kernel_launch(void* const* d_in, const int* in_sizes, int n_in,
                              void* d_out, int out_size) {
    const float* fmaps = (const float*)d_in[0];
    const float* boxes = (const float*)d_in[1];
    const int*   pids  = (const int*)d_in[2];
    const float* w1a   = (const float*)d_in[3];
    const float* b1a   = (const float*)d_in[4];
    const float* w1b   = (const float*)d_in[5];
    const float* b1b   = (const float*)d_in[6];
    const float* fcw   = (const float*)d_in[7];
    const float* fcb   = (const float*)d_in[8];
    float* out = (float*)d_out;

    __half *pA0, *pB1, *pYh, *pB2;
    float *pP, *pC2p;
    cudaGetSymbolAddress((void**)&pA0, g_A0);
    cudaGetSymbolAddress((void**)&pB1, g_B1);
    cudaGetSymbolAddress((void**)&pYh, g_yh);
    cudaGetSymbolAddress((void**)&pB2, g_B2);
    cudaGetSymbolAddress((void**)&pP,  g_P);
    cudaGetSymbolAddress((void**)&pC2p, g_C2p);

    cudaFuncSetAttribute(gemm_mma, cudaFuncAttributeMaxDynamicSharedMemorySize, 36864);
    cudaFuncSetAttribute(prep_all, cudaFuncAttributeMaxDynamicSharedMemorySize, 55296);

    // fused prep: roi+im2col | w1a | w1b | map — all independent
    prep_all<<<961, 256, 55296>>>(fmaps, boxes, pids, w1a, w1b);

    // G1 split-K=2: P[z][1728x1536] = A[1728x9216] * B[1536x9216]^T
    gemm_mma<<<dim3(N1/128, M1/64, SPLIT1), 256, 36864>>>(
        pA0, pB1, KIT1, K1, K1, 1, 1, pP, N1, (size_t)M1*N1);

    combine_kernel<<<NBOX*5, 256>>>(b1a);

    // G2 split-K=8: C2p[z][576x256] = y * B2^T, row remap (r/3)*5 + r%3
    gemm_mma<<<dim3(N2/128, M2/64, SPLIT2), 256, 36864>>>(
        pYh, pB2, KIT2, 4608, K2, 3, 5, pC2p, N2, (size_t)M2*N2);

    maxfc_kernel<<<NBOX, 256>>>(b1b, fcw, fcb, out);
}

// round 11
// speedup vs baseline: 6.6203x; 1.0582x over previous
#include <cuda_runtime.h>
#include <cuda_fp16.h>
#include <cstdint>

// ---------------- problem constants ----------------
#define F_    32
#define B_    6
#define C_    1024
#define HF    14
#define NB    27
#define T_    5
#define OUTP  3
#define SPAT  9
#define NBOX  (F_*B_)           // 192
#define K1    (C_*SPAT)         // 9216
#define N1    (3*512)           // 1536
#define M1    (NBOX*SPAT)       // 1728 = 27*64
#define K2    (512*27)          // 13824
#define M2    (NBOX*3)          // 576 = 9*64
#define N2    256
#define SPLIT1 4
#define KIT1  72                // 9216/4/32
#define SPLIT2 16
#define KIT2  27                // 13824/16/32

// ---------------- scratch ----------------
__device__ int   g_map[NBOX*T_];
__device__ __align__(16) __half g_A0[(size_t)M1*K1];   // im2col fp16
__device__ __align__(16) __half g_B1[(size_t)N1*K1];   // w1a [n][k] fp16
__device__ float g_P [(size_t)SPLIT1*M1*N1];           // G1 split-K partials
__device__ __align__(16) __half g_yh[(size_t)NBOX*5*4608];
__device__ __align__(16) __half g_B2[(size_t)N2*K2];   // w1b [n][k] fp16
__device__ float g_C2p[(size_t)SPLIT2*M2*N2];

// ---------------- helpers ----------------
__device__ __forceinline__ void cpasync16(uint32_t dst, const void* src) {
    asm volatile("cp.async.cg.shared.global [%0], [%1], 16;"
                 :: "r"(dst), "l"(__cvta_generic_to_global(src)) : "memory");
}
__device__ __forceinline__ uint32_t smem_u32(const void* p) {
    uint32_t a;
    asm("{ .reg .u64 t; cvta.to.shared.u64 t, %1; cvt.u32.u64 %0, t; }"
        : "=r"(a) : "l"(p));
    return a;
}
#define CP_COMMIT() asm volatile("cp.async.commit_group;" ::: "memory")
#define CP_WAIT2()  asm volatile("cp.async.wait_group 2;" ::: "memory")
#define LDSM4(rr, a) asm volatile( \
    "ldmatrix.sync.aligned.m8n8.x4.shared.b16 {%0,%1,%2,%3}, [%4];" \
    : "=r"((rr)[0]),"=r"((rr)[1]),"=r"((rr)[2]),"=r"((rr)[3]) : "r"(a))
__device__ __forceinline__ void mma_f16(float* d, const uint32_t* a,
                                        uint32_t b0, uint32_t b1) {
    asm volatile(
        "mma.sync.aligned.m16n8k16.row.col.f32.f16.f16.f32 "
        "{%0,%1,%2,%3}, {%4,%5,%6,%7}, {%8,%9}, {%0,%1,%2,%3};"
        : "+f"(d[0]), "+f"(d[1]), "+f"(d[2]), "+f"(d[3])
        : "r"(a[0]), "r"(a[1]), "r"(a[2]), "r"(a[3]), "r"(b0), "r"(b1));
}
// swizzled byte offset within rows x 32 fp16 tile (64B rows, 16B chunks)
__device__ __forceinline__ uint32_t swz(int row, int ckl) {
    return (uint32_t)row*64u + (uint32_t)((ckl ^ (row & 3)) << 4);
}
__device__ __forceinline__ uint32_t pack2(__half a, __half b) {
    __half2 h2 = __halves2half2(a, b);
    return *(uint32_t*)&h2;
}

// ---------------- fused prep: roi+im2col | w1a | w1b | map ----------------
__global__ void __launch_bounds__(256)
prep_all(const float* __restrict__ fmaps, const float* __restrict__ boxes,
         const int* __restrict__ person_ids,
         const float* __restrict__ w1a, const float* __restrict__ w1b) {
    extern __shared__ char dyn[];
    const int bb = blockIdx.x;
    const int tid = threadIdx.x;

    if (bb < 192) {
        // ---------- ROI align + im2col ----------
        __half* sroi = (__half*)dyn;             // 9216 halves = 18KB
        __shared__ int   sy0[6], sy1[6], sx0[6], sx1[6];
        __shared__ float sly[6], slx[6];
        int nb = bb;
        int f  = nb / B_;
        if (tid < 12) {
            int  j   = tid % 6;
            bool isx = tid >= 6;
            float x1 = boxes[nb*4+0], y1 = boxes[nb*4+1];
            float x2 = boxes[nb*4+2], y2 = boxes[nb*4+3];
            float bw = fmaxf(x2 - x1, 1.0f) / (float)OUTP;
            float bh = fmaxf(y2 - y1, 1.0f) / (float)OUTP;
            float gj = (float)(j >> 1) + ((float)(j & 1) + 0.5f) * 0.5f;
            if (isx) {
                float xs  = x1 + bw * gj;
                float x0f = fminf(fmaxf(floorf(xs), 0.f), (float)(HF-1));
                float lx  = fminf(fmaxf(xs - x0f, 0.f), 1.f);
                int x0 = (int)x0f;
                sx0[j] = x0; sx1[j] = min(x0+1, HF-1); slx[j] = lx;
            } else {
                float ys  = y1 + bh * gj;
                float y0f = fminf(fmaxf(floorf(ys), 0.f), (float)(HF-1));
                float ly  = fminf(fmaxf(ys - y0f, 0.f), 1.f);
                int y0 = (int)y0f;
                sy0[j] = y0; sy1[j] = min(y0+1, HF-1); sly[j] = ly;
            }
        }
        __syncthreads();
        const float* base = fmaps + (size_t)f * C_ * HF * HF;
        for (int idx = tid; idx < C_*SPAT; idx += 256) {
            int c = idx / SPAT, o = idx % SPAT;
            int oi = o / 3, oj = o % 3;
            const float* fm = base + (size_t)c * HF * HF;
            float acc = 0.f;
            #pragma unroll
            for (int s = 0; s < 4; s++) {
                int jy = oi*2 + (s >> 1);
                int jx = oj*2 + (s & 1);
                float ly = sly[jy], lx = slx[jx];
                int y0 = sy0[jy], y1i = sy1[jy], x0 = sx0[jx], x1i = sx1[jx];
                acc += fm[y0*HF + x0]  * (1.f-ly)*(1.f-lx)
                     + fm[y0*HF + x1i] * (1.f-ly)*lx
                     + fm[y1i*HF + x0] * ly*(1.f-lx)
                     + fm[y1i*HF + x1i]* ly*lx;
            }
            sroi[idx] = __float2half(acc * 0.25f);
        }
        __syncthreads();
        const __half hz = __float2half(0.f);
        #pragma unroll
        for (int sp = 0; sp < SPAT; sp++) {
            int h = sp / 3, w = sp % 3;
            uint32_t* dst = (uint32_t*)(g_A0 + ((size_t)(nb*9 + sp)) * K1);
            for (int jj = tid; jj < K1/2; jj += 256) {
                int j0 = 2*jj, j1 = 2*jj + 1;
                int ci0 = j0 / 9, t0 = j0 % 9;
                int ci1 = j1 / 9, t1 = j1 % 9;
                int h0 = h + t0/3 - 1, w0 = w + t0%3 - 1;
                int h1 = h + t1/3 - 1, w1 = w + t1%3 - 1;
                __half v0 = (h0 >= 0 && h0 < 3 && w0 >= 0 && w0 < 3)
                            ? sroi[ci0*9 + h0*3 + w0] : hz;
                __half v1 = (h1 >= 0 && h1 < 3 && w1 >= 0 && w1 < 3)
                            ? sroi[ci1*9 + h1*3 + w1] : hz;
                dst[jj] = pack2(v0, v1);
            }
        }
    } else if (bb < 704) {
        // ---------- w1a: linear smem fp16, gather on read ----------
        __half* sh = (__half*)dyn;               // 27648 halves = 55296B
        int co = bb - 192;
        const float* src = w1a + (size_t)co * 27648;
        for (int i = tid; i < 27648; i += 256)
            sh[i] = __float2half(src[i]);        // conflict-free STS
        __syncthreads();
        #pragma unroll
        for (int kd = 0; kd < 3; kd++) {
            uint32_t* dst = (uint32_t*)(g_B1 + ((size_t)(kd*512 + co)) * 9216);
            const int kb = kd * 9;
            for (int jj = tid; jj < 4608; jj += 256) {
                int j0 = 2*jj, j1 = j0 + 1;
                int ci0 = j0 / 9, t0 = j0 % 9;
                int ci1 = j1 / 9, t1 = j1 % 9;
                dst[jj] = pack2(sh[ci0*27 + kb + t0], sh[ci1*27 + kb + t1]);
            }
        }
    } else if (bb < 960) {
        // ---------- w1b: linear smem fp16, gather on read ----------
        __half* sh = (__half*)dyn;               // 13824 halves = 27648B
        int n = bb - 704;
        const float* src = w1b + (size_t)n * 13824;
        for (int i = tid; i < 13824; i += 256)
            sh[i] = __float2half(src[i]);
        __syncthreads();
        uint32_t* dst = (uint32_t*)(g_B2 + (size_t)n * 13824);
        for (int jj = tid; jj < 6912; jj += 256) {
            int j = 2*jj;
            int q = j >> 9, ci = j & 511;        // pairs never cross q
            dst[jj] = pack2(sh[ci*27 + q], sh[(ci+1)*27 + q]);
        }
    } else {
        // ---------- temporal index + person matching ----------
        int n = tid;
        if (n < NBOX) {
            int f = n / B_, b = n % B_;
            int pid = person_ids[f*B_ + b];
            int start = max(f - T_/2, 0);
            int end   = min(start + T_ - 1, F_ - 1);
            for (int t = 0; t < T_; t++) {
                int g = (int)((float)start + (float)(t*(end-start)) / (float)(T_-1));
                int m = -1;
                for (int bp = 0; bp < B_; bp++)
                    if (person_ids[g*B_ + bp] == pid) m = g*B_ + bp;
                g_map[n*T_ + t] = m;
            }
        }
    }
}

// ---------------- pipelined warp-MMA GEMM (fp16, fp32 acc) ------
// CTA tile 64x128, BK=32, 4-stage cp.async, ONE barrier/iter, 256 thr.
// Stage (12KB): A @0 (4KB), B @4096 (8KB). Exact tiling, no bounds checks.
__global__ void __launch_bounds__(256, 2)
gemm_mma(const __half* __restrict__ A0, const __half* __restrict__ B0,
         int kIters, size_t aStride, size_t bStride,
         int rdiv, int rmul,
         float* __restrict__ C, int ldc, size_t cSplit) {
    extern __shared__ char smem[];
    const uint32_t sb = smem_u32(smem);
    const int tid = threadIdx.x;
    const int lane = tid & 31, wid = tid >> 5;
    const int warp_m = wid & 1, warp_n = wid >> 1;
    const int g = lane >> 2, t4 = lane & 3;
    const int row0 = blockIdx.y * 64;
    const int col0 = blockIdx.x * 128;
    const int kStart = blockIdx.z * kIters * 32;

    const int rA = tid >> 2, ckA = tid & 3;
    const uint32_t dstA = swz(rA, ckA);
    const int grA = row0 + rA;
    const size_t roffA = (size_t)((grA / rdiv) * rmul + (grA % rdiv)) * aStride
                       + (size_t)(ckA * 8);
    const int rB0 = tid >> 2, ckB0 = tid & 3;
    const int rB1 = (tid + 256) >> 2, ckB1 = tid & 3;
    const uint32_t dstB0 = swz(rB0, ckB0);
    const uint32_t dstB1 = swz(rB1, ckB1);
    const size_t goffB0 = (size_t)(col0 + rB0) * bStride + (size_t)(ckB0 * 8);
    const size_t goffB1 = (size_t)(col0 + rB1) * bStride + (size_t)(ckB1 * 8);

    float acc[2][4][4];
    #pragma unroll
    for (int mt = 0; mt < 2; mt++)
        #pragma unroll
        for (int ni = 0; ni < 4; ni++)
            #pragma unroll
            for (int q = 0; q < 4; q++) acc[mt][ni][q] = 0.f;

    // prologue: stages 0..2
    #pragma unroll
    for (int p = 0; p < 3; p++) {
        uint32_t st = sb + p * 12288u;
        int kOff = kStart + p * 32;
        cpasync16(st +    0 + dstA, A0 + roffA + kOff);
        cpasync16(st + 4096 + dstB0, B0 + goffB0 + kOff);
        cpasync16(st + 4096 + dstB1, B0 + goffB1 + kOff);
        CP_COMMIT();
    }

    int sIdx = 0;
    for (int it = 0; it < kIters; it++) {
        CP_WAIT2();            // stage sIdx ready (2 newer groups pending)
        __syncthreads();       // visibility + read/overwrite fence

        // prefetch stage (it+3) — always commit to keep group accounting
        if (it + 3 < kIters) {
            int pIdx = (sIdx + 3) & 3;
            uint32_t st = sb + pIdx * 12288u;
            int kOff = kStart + (it + 3) * 32;
            cpasync16(st +    0 + dstA, A0 + roffA + kOff);
            cpasync16(st + 4096 + dstB0, B0 + goffB0 + kOff);
            cpasync16(st + 4096 + dstB1, B0 + goffB1 + kOff);
        }
        CP_COMMIT();

        const uint32_t st = sb + sIdx * 12288u;
        #pragma unroll
        for (int ksub = 0; ksub < 2; ksub++) {
            const int ckl = ksub*2 + (lane >> 4);
            uint32_t ah[2][4];
            #pragma unroll
            for (int mt = 0; mt < 2; mt++) {
                int row = warp_m*32 + mt*16 + (lane & 15);
                LDSM4(ah[mt], st + swz(row, ckl));
            }
            #pragma unroll
            for (int ni2 = 0; ni2 < 2; ni2++) {
                int row = warp_n*32 + ni2*16 + (lane & 15);
                uint32_t bh[4];
                LDSM4(bh, st + 4096 + swz(row, ckl));
                #pragma unroll
                for (int h = 0; h < 2; h++) {
                    const int ni = ni2*2 + h;
                    #pragma unroll
                    for (int mt = 0; mt < 2; mt++)
                        mma_f16(acc[mt][ni], ah[mt], bh[h], bh[2+h]);
                }
            }
        }
        sIdx = (sIdx + 1) & 3;
    }

    float* Cb = C + (size_t)blockIdx.z * cSplit;
    #pragma unroll
    for (int mt = 0; mt < 2; mt++) {
        int r_0 = row0 + warp_m*32 + mt*16 + g;
        int r_1 = r_0 + 8;
        #pragma unroll
        for (int ni = 0; ni < 4; ni++) {
            int cc = col0 + warp_n*32 + ni*8 + t4*2;
            *(float2*)(Cb + (size_t)r_0*ldc + cc) =
                make_float2(acc[mt][ni][0], acc[mt][ni][1]);
            *(float2*)(Cb + (size_t)r_1*ldc + cc) =
                make_float2(acc[mt][ni][2], acc[mt][ni][3]);
        }
    }
}

// ---------------- combine split-K P + depth taps + bias + relu -> y -----
__global__ void combine_kernel(const float* __restrict__ b1a) {
    int bid = blockIdx.x;           // n*5 + d
    int n = bid / 5, d = bid % 5;
    __shared__ int mm[3];
    if (threadIdx.x < 3) {
        int t = d + threadIdx.x - 1;
        mm[threadIdx.x] = (t >= 0 && t < 5) ? g_map[n*5 + t] : -1;
    }
    __syncthreads();
    const size_t PS = (size_t)M1 * N1;
    for (int idx = threadIdx.x; idx < 9*512; idx += blockDim.x) {
        int sp = idx >> 9, co = idx & 511;
        float acc = b1a[co];
        #pragma unroll
        for (int kd = 0; kd < 3; kd++) {
            int m = mm[kd];
            if (m >= 0) {
                size_t o = ((size_t)(m*9 + sp))*N1 + kd*512 + co;
                #pragma unroll
                for (int z = 0; z < SPLIT1; z++)
                    acc += g_P[(size_t)z*PS + o];
            }
        }
        g_yh[(size_t)bid*4608 + idx] = __float2half(fmaxf(acc, 0.f));
    }
}

// ---------------- reduce split-K + bias/relu/max/FC ------------
__global__ void maxfc_kernel(const float* __restrict__ b1b,
                             const float* __restrict__ fcw,
                             const float* __restrict__ fcb,
                             float* __restrict__ out) {
    int n = blockIdx.x;
    __shared__ float z[256];
    int c = threadIdx.x;
    float v = -3.4e38f;
    #pragma unroll
    for (int dd = 0; dd < 3; dd++) {
        float s = 0.f;
        #pragma unroll
        for (int zz = 0; zz < SPLIT2; zz++)
            s += g_C2p[(size_t)zz*M2*N2 + (size_t)(n*3 + dd)*N2 + c];
        v = fmaxf(v, s);
    }
    z[c] = fmaxf(v + b1b[c], 0.f);
    __syncthreads();
    int warp = threadIdx.x >> 5, lane = threadIdx.x & 31;
    for (int j = warp; j < NB; j += 8) {
        float s = 0.f;
        #pragma unroll
        for (int q = 0; q < 8; q++)
            s += z[lane + q*32] * fcw[j*256 + lane + q*32];
        #pragma unroll
        for (int off = 16; off; off >>= 1)
            s += __shfl_xor_sync(0xffffffffu, s, off);
        if (lane == 0) out[n*NB + j] = s + fcb[j];
    }
}

// ---------------- launch ----------------
extern "C" void kernel_launch(void* const* d_in, const int* in_sizes, int n_in,
                              void* d_out, int out_size) {
    const float* fmaps = (const float*)d_in[0];
    const float* boxes = (const float*)d_in[1];
    const int*   pids  = (const int*)d_in[2];
    const float* w1a   = (const float*)d_in[3];
    const float* b1a   = (const float*)d_in[4];
    const float* w1b   = (const float*)d_in[5];
    const float* b1b   = (const float*)d_in[6];
    const float* fcw   = (const float*)d_in[7];
    const float* fcb   = (const float*)d_in[8];
    float* out = (float*)d_out;

    __half *pA0, *pB1, *pYh, *pB2;
    float *pP, *pC2p;
    cudaGetSymbolAddress((void**)&pA0, g_A0);
    cudaGetSymbolAddress((void**)&pB1, g_B1);
    cudaGetSymbolAddress((void**)&pYh, g_yh);
    cudaGetSymbolAddress((void**)&pB2, g_B2);
    cudaGetSymbolAddress((void**)&pP,  g_P);
    cudaGetSymbolAddress((void**)&pC2p, g_C2p);

    cudaFuncSetAttribute(gemm_mma, cudaFuncAttributeMaxDynamicSharedMemorySize, 49152);
    cudaFuncSetAttribute(prep_all, cudaFuncAttributeMaxDynamicSharedMemorySize, 55296);

    // fused prep: roi+im2col | w1a | w1b | map — all independent
    prep_all<<<961, 256, 55296>>>(fmaps, boxes, pids, w1a, w1b);

    // G1 split-K=4: P[z][1728x1536] = A[1728x9216] * B[1536x9216]^T
    gemm_mma<<<dim3(N1/128, M1/64, SPLIT1), 256, 49152>>>(
        pA0, pB1, KIT1, K1, K1, 1, 1, pP, N1, (size_t)M1*N1);

    combine_kernel<<<NBOX*5, 256>>>(b1a);

    // G2 split-K=16: C2p[z][576x256] = y * B2^T, row remap (r/3)*5 + r%3
    gemm_mma<<<dim3(N2/128, M2/64, SPLIT2), 256, 49152>>>(
        pYh, pB2, KIT2, 4608, K2, 3, 5, pC2p, N2, (size_t)M2*N2);

    maxfc_kernel<<<NBOX, 256>>>(b1b, fcw, fcb, out);
}